// round 8
// baseline (speedup 1.0000x reference)
#include <cuda_runtime.h>
#include <cuda_bf16.h>
#include <math.h>
#include <stdint.h>

#define BATCH 2
#define NPTS 4096
#define DM 512
#define NH 8
#define DH 64
#define KNB 16
#define ROWS (BATCH * NPTS)   // 8192

// ---------------- scratch (device globals; no allocation allowed) ----------------
__device__ float g_Q[ROWS * DM];
__device__ float g_K[ROWS * DM];
__device__ float g_V[ROWS * DM];
__device__ float g_tmp[ROWS * DM];
__device__ int   g_idx[ROWS * KNB];
__device__ float4 g_pos4[ROWS];                 // padded positions (x,y,z,0)
__device__ __nv_bfloat16 g_Ahi[ROWS * DM];      // activation split (feat, later att)
__device__ __nv_bfloat16 g_Alo[ROWS * DM];
__device__ __nv_bfloat16 g_Bhi[4 * DM * DM];    // transposed weight split [z][n*DM+k]
__device__ __nv_bfloat16 g_Blo[4 * DM * DM];

// ---------------- helpers --------------------------------------------------------
__device__ __forceinline__ uint32_t smem_u32(const void* p) {
    uint32_t a;
    asm("{ .reg .u64 t; cvta.to.shared.u64 t, %1; cvt.u32.u64 %0, t; }"
        : "=r"(a) : "l"(p));
    return a;
}
#define CP16(dst, src) \
    asm volatile("cp.async.cg.shared.global [%0], [%1], 16;" :: "r"(dst), "l"(src))
#define CP_COMMIT() asm volatile("cp.async.commit_group;" ::: "memory")
#define CP_WAIT(n)  asm volatile("cp.async.wait_group %0;" :: "n"(n) : "memory")

__device__ __forceinline__ void ldmx4(uint32_t* r, uint32_t addr) {
    asm volatile("ldmatrix.sync.aligned.m8n8.x4.shared.b16 {%0,%1,%2,%3}, [%4];"
                 : "=r"(r[0]), "=r"(r[1]), "=r"(r[2]), "=r"(r[3]) : "r"(addr));
}
__device__ __forceinline__ void mma16816(float* c, const uint32_t* a, const uint32_t* b) {
    asm volatile(
        "mma.sync.aligned.m16n8k16.row.col.f32.bf16.bf16.f32 "
        "{%0,%1,%2,%3}, {%4,%5,%6,%7}, {%8,%9}, {%0,%1,%2,%3};"
        : "+f"(c[0]), "+f"(c[1]), "+f"(c[2]), "+f"(c[3])
        : "r"(a[0]), "r"(a[1]), "r"(a[2]), "r"(a[3]), "r"(b[0]), "r"(b[1]));
}

// ---------------- prep: split feat + transpose/split weights + pos4 --------------
__global__ __launch_bounds__(256) void prep_kernel(const float* __restrict__ feat,
                                                   const float* __restrict__ pos,
                                                   const float* __restrict__ W0,
                                                   const float* __restrict__ W1,
                                                   const float* __restrict__ W2,
                                                   const float* __restrict__ W3) {
    __shared__ float t[32][33];
    if (blockIdx.x < 4096) {                      // split feat
        int i = blockIdx.x * blockDim.x + threadIdx.x;
        float4 v = *(const float4*)&feat[(size_t)i * 4];
        __nv_bfloat16 h0 = __float2bfloat16(v.x), h1 = __float2bfloat16(v.y);
        __nv_bfloat16 h2 = __float2bfloat16(v.z), h3 = __float2bfloat16(v.w);
        __nv_bfloat16 l0 = __float2bfloat16(v.x - __bfloat162float(h0));
        __nv_bfloat16 l1 = __float2bfloat16(v.y - __bfloat162float(h1));
        __nv_bfloat16 l2 = __float2bfloat16(v.z - __bfloat162float(h2));
        __nv_bfloat16 l3 = __float2bfloat16(v.w - __bfloat162float(h3));
        uint2 h, l;
        h.x = ((unsigned)__bfloat16_as_ushort(h1) << 16) | __bfloat16_as_ushort(h0);
        h.y = ((unsigned)__bfloat16_as_ushort(h3) << 16) | __bfloat16_as_ushort(h2);
        l.x = ((unsigned)__bfloat16_as_ushort(l1) << 16) | __bfloat16_as_ushort(l0);
        l.y = ((unsigned)__bfloat16_as_ushort(l3) << 16) | __bfloat16_as_ushort(l2);
        *(uint2*)&g_Ahi[(size_t)i * 4] = h;
        *(uint2*)&g_Alo[(size_t)i * 4] = l;
    } else if (blockIdx.x < 4096 + 1024) {        // transpose+split weights
        int id = blockIdx.x - 4096;               // 16 x 16 x 4
        int z = id >> 8;
        int by = ((id >> 4) & 15) * 32, bx = (id & 15) * 32;
        const float* src = (z == 0) ? W0 : (z == 1) ? W1 : (z == 2) ? W2 : W3;
        size_t zoff = (size_t)z * DM * DM;
        int tx = threadIdx.x & 31, ty = threadIdx.x >> 5;   // 32 x 8
#pragma unroll
        for (int i = 0; i < 32; i += 8)
            t[ty + i][tx] = src[(size_t)(by + ty + i) * DM + bx + tx];
        __syncthreads();
#pragma unroll
        for (int i = 0; i < 32; i += 8) {
            float v = t[tx][ty + i];
            __nv_bfloat16 h = __float2bfloat16(v);
            __nv_bfloat16 l = __float2bfloat16(v - __bfloat162float(h));
            size_t o = zoff + (size_t)(bx + ty + i) * DM + by + tx;
            g_Bhi[o] = h;
            g_Blo[o] = l;
        }
    } else {                                      // pos -> float4 (32 CTAs)
        int i = (blockIdx.x - 4096 - 1024) * blockDim.x + threadIdx.x;  // 0..8191
        g_pos4[i] = make_float4(pos[i * 3 + 0], pos[i * 3 + 1], pos[i * 3 + 2], 0.0f);
    }
}

// ---------------- HMMA bf16x3 GEMM body (single-sync double buffer) --------------
#define BKC 32
#define NCH (DM / BKC)        // 16
#define ST_A_HI 0
#define ST_A_LO 8192
#define ST_B_HI 16384
#define ST_B_LO 24576
#define STAGE 32768
#define GEMM_SMEM (2 * STAGE)

__device__ __forceinline__ void tc_gemm_body(char* smem,
                                             const __nv_bfloat16* __restrict__ Ahi,
                                             const __nv_bfloat16* __restrict__ Alo,
                                             const __nv_bfloat16* __restrict__ Bhi,
                                             const __nv_bfloat16* __restrict__ Blo,
                                             float* __restrict__ C,
                                             int bm, int bn) {
    uint32_t sb = smem_u32(smem);
    int tid = threadIdx.x;             // 256
    int wid = tid >> 5, lane = tid & 31;
    int warp_m = wid & 3, warp_n = wid >> 2;       // 4 x 2 warps -> 32x64 warp tile

    int r0 = (tid * 2) >> 2, c0 = (tid * 2) & 3;
    int r1 = (tid * 2 + 1) >> 2, c1 = (tid * 2 + 1) & 3;
    uint32_t d0 = (uint32_t)(r0 * 64 + ((c0 ^ ((r0 >> 1) & 3)) << 4));
    uint32_t d1 = (uint32_t)(r1 * 64 + ((c1 ^ ((r1 >> 1) & 3)) << 4));

    float c[2][8][4];
#pragma unroll
    for (int mt = 0; mt < 2; mt++)
#pragma unroll
        for (int nt = 0; nt < 8; nt++)
#pragma unroll
            for (int e = 0; e < 4; e++) c[mt][nt][e] = 0.0f;

    int arow = warp_m * 32 + (lane & 15);
    int akh  = lane >> 4;
    int axor = (arow >> 1) & 3;
    int brow = warp_n * 64 + (lane & 7) + ((lane >> 4) << 3);
    int bkh  = (lane >> 3) & 1;
    int bxor = (brow >> 1) & 3;

    // prologue: stage 0
#pragma unroll
    for (int arr = 0; arr < 4; arr++) {
        const __nv_bfloat16* g = (arr == 0) ? Ahi : (arr == 1) ? Alo
                               : (arr == 2) ? Bhi : Blo;
        int rowbase = (arr < 2) ? bm : bn;
        uint32_t dst = sb + arr * 8192;
        CP16(dst + d0, &g[(size_t)(rowbase + r0) * DM + c0 * 8]);
        CP16(dst + d1, &g[(size_t)(rowbase + r1) * DM + c1 * 8]);
    }
    CP_COMMIT();

    for (int kc = 0; kc < NCH; kc++) {
        CP_WAIT(0);
        __syncthreads();   // stage kc ready AND all warps done reading stage kc-1
        if (kc + 1 < NCH) {
            uint32_t stg = sb + ((kc + 1) & 1) * STAGE;
            int koff = (kc + 1) * BKC;
#pragma unroll
            for (int arr = 0; arr < 4; arr++) {
                const __nv_bfloat16* g = (arr == 0) ? Ahi : (arr == 1) ? Alo
                                       : (arr == 2) ? Bhi : Blo;
                int rowbase = (arr < 2) ? bm : bn;
                uint32_t dst = stg + arr * 8192;
                CP16(dst + d0, &g[(size_t)(rowbase + r0) * DM + koff + c0 * 8]);
                CP16(dst + d1, &g[(size_t)(rowbase + r1) * DM + koff + c1 * 8]);
            }
            CP_COMMIT();
        }

        uint32_t stg = sb + (kc & 1) * STAGE;
#pragma unroll
        for (int ks = 0; ks < 2; ks++) {
            uint32_t ah[2][4], al[2][4];
#pragma unroll
            for (int mt = 0; mt < 2; mt++) {
                uint32_t rbase = stg + (uint32_t)((arow + mt * 16) * 64);
                uint32_t ch = (uint32_t)(((ks * 2 + akh) ^ axor) << 4);
                ldmx4(ah[mt], rbase + ST_A_HI + ch);
                ldmx4(al[mt], rbase + ST_A_LO + ch);
            }
#pragma unroll
            for (int np = 0; np < 4; np++) {
                uint32_t rbase = stg + (uint32_t)((brow + np * 16) * 64);
                uint32_t ch = (uint32_t)(((ks * 2 + bkh) ^ bxor) << 4);
                uint32_t bh[4], bl[4];
                ldmx4(bh, rbase + ST_B_HI + ch);
                ldmx4(bl, rbase + ST_B_LO + ch);
#pragma unroll
                for (int mt = 0; mt < 2; mt++) {
                    mma16816(c[mt][np * 2 + 0], ah[mt], &bh[0]);
                    mma16816(c[mt][np * 2 + 1], ah[mt], &bh[2]);
                    mma16816(c[mt][np * 2 + 0], ah[mt], &bl[0]);
                    mma16816(c[mt][np * 2 + 1], ah[mt], &bl[2]);
                    mma16816(c[mt][np * 2 + 0], al[mt], &bh[0]);
                    mma16816(c[mt][np * 2 + 1], al[mt], &bh[2]);
                }
            }
        }
    }

    int gid = lane >> 2, t4 = lane & 3;
#pragma unroll
    for (int mt = 0; mt < 2; mt++) {
        int r = bm + warp_m * 32 + mt * 16 + gid;
#pragma unroll
        for (int nt = 0; nt < 8; nt++) {
            int col = bn + warp_n * 64 + nt * 8 + t4 * 2;
            *(float2*)&C[(size_t)r * DM + col] =
                make_float2(c[mt][nt][0], c[mt][nt][1]);
            *(float2*)&C[(size_t)(r + 8) * DM + col] =
                make_float2(c[mt][nt][2], c[mt][nt][3]);
        }
    }
}

// ---------------- fused: QKV GEMMs + kNN, interleaved CTA groups -----------------
#define QW 8
__global__ __launch_bounds__(256, 2) void fused_qkv_knn(float* __restrict__ Cq,
                                                        float* __restrict__ Ck,
                                                        float* __restrict__ Cv) {
    extern __shared__ __align__(128) char smem[];
    int g7 = blockIdx.x / 7, r7 = blockIdx.x % 7;

    if (r7 < 3) {
        // ---- GEMM CTA ----
        int id = g7 * 3 + r7;              // 0..767
        int z  = id >> 8;                  // 0..2
        int rem = id & 255;
        int bm = (rem >> 2) * 128, bn = (rem & 3) * 128;
        float* C = (z == 0) ? Cq : (z == 1) ? Ck : Cv;
        tc_gemm_body(smem, g_Ahi, g_Alo,
                     g_Bhi + (size_t)z * DM * DM, g_Blo + (size_t)z * DM * DM,
                     C, bm, bn);
    } else {
        // ---- kNN CTA: warp per query, global-threshold pruned top-17 ----
        unsigned long long (*smrg)[32][KNB + 2] =
            (unsigned long long (*)[32][KNB + 2])smem;
        int warp = threadIdx.x >> 5, lane = threadIdx.x & 31;
        int q = (g7 * 4 + (r7 - 3)) * QW + warp;    // 0..8191
        int b = q >> 12;
        int base = b << 12;
        float4 qp = g_pos4[q];

        unsigned long long key[KNB + 1];
#pragma unroll
        for (int i = 0; i < KNB + 1; i++) key[i] = 0xFFFFFFFFFFFFFFFFull;
        unsigned long long Tb = 0xFFFFFFFFFFFFFFFFull;

        for (int step = 0; step < NPTS / 32; step++) {
            if ((step & 7) == 0) {
                // refresh warp-global prune threshold: min over lanes of key[16]
                unsigned long long w = key[KNB];
#pragma unroll
                for (int off = 16; off; off >>= 1) {
                    unsigned long long o = __shfl_xor_sync(0xffffffffu, w, off);
                    if (o < w) w = o;
                }
                Tb = w;
            }
            int j = step * 32 + lane;
            float4 p = g_pos4[base + j];
            float dx = qp.x - p.x;
            float dy = qp.y - p.y;
            float dz = qp.z - p.z;
            float d = fmaf(dx, dx, fmaf(dy, dy, dz * dz));
            unsigned long long kk =
                ((unsigned long long)__float_as_uint(d) << 32) | (unsigned)j;
            if (kk < Tb) {
#pragma unroll
                for (int p2 = KNB; p2 >= 1; p2--) {
                    unsigned long long lower = key[p2 - 1];
                    unsigned long long cur   = key[p2];
                    key[p2] = (kk >= cur) ? cur : ((kk >= lower) ? kk : lower);
                }
                key[0] = (kk < key[0]) ? kk : key[0];
            }
        }

#pragma unroll
        for (int i = 0; i < KNB + 1; i++) smrg[warp][lane][i] = key[i];
        smrg[warp][lane][KNB + 1] = 0xFFFFFFFFFFFFFFFFull;
        __syncwarp();

        int p = 0;
        unsigned long long head = smrg[warp][lane][0];
        for (int out = 0; out < KNB + 1; out++) {
            unsigned long long m = head;
#pragma unroll
            for (int off = 16; off; off >>= 1) {
                unsigned long long o = __shfl_xor_sync(0xffffffffu, m, off);
                if (o < m) m = o;
            }
            if (out > 0 && lane == 0)
                g_idx[q * KNB + out - 1] = (int)(unsigned)m;
            if (head == m) { p++; head = smrg[warp][lane][p]; }
        }
    }
}

__global__ __launch_bounds__(256, 2) void gemm_o_tc(float* __restrict__ C) {
    extern __shared__ __align__(128) char smem[];
    tc_gemm_body(smem, g_Ahi, g_Alo,
                 g_Bhi + (size_t)3 * DM * DM, g_Blo + (size_t)3 * DM * DM,
                 C, blockIdx.y * 128, blockIdx.x * 128);
}

// ---------------- attention: warp per (row, head); writes bf16 hi/lo splits -----
__global__ __launch_bounds__(256) void attn_kernel(const float* __restrict__ pos,
                                                   const float* __restrict__ Wpos,
                                                   const float* __restrict__ bpos,
                                                   const float* __restrict__ temp) {
    int gw   = (blockIdx.x * blockDim.x + threadIdx.x) >> 5;
    int lane = threadIdx.x & 31;
    int row  = gw >> 3;
    int h    = gw & 7;
    int b    = row >> 12;
    int n    = row & (NPTS - 1);
    const float* posb = pos + (size_t)b * NPTS * 3;
    int base = (b << 12);

    int j = 0;
    float rx = 0.f, ry = 0.f, rz = 0.f;
    float px = posb[n * 3 + 0], py = posb[n * 3 + 1], pz = posb[n * 3 + 2];
    if (lane < KNB) {
        j  = g_idx[row * KNB + lane];
        rx = px - posb[j * 3 + 0];
        ry = py - posb[j * 3 + 1];
        rz = pz - posb[j * 3 + 2];
    }

    float invT = 1.0f / temp[0];
    float2 q = *(const float2*)&g_Q[(size_t)row * DM + h * DH + 2 * lane];
    q.x *= invT; q.y *= invT;
    float2 w0 = *(const float2*)&Wpos[0 * 128 + 2 * lane];
    float2 w1 = *(const float2*)&Wpos[1 * 128 + 2 * lane];
    float2 w2 = *(const float2*)&Wpos[2 * 128 + 2 * lane];
    float2 bp = *(const float2*)&bpos[2 * lane];

    float myscore = 0.0f;
#pragma unroll
    for (int k = 0; k < KNB; k++) {
        int   jk  = __shfl_sync(0xffffffffu, j,  k);
        float rxk = __shfl_sync(0xffffffffu, rx, k);
        float ryk = __shfl_sync(0xffffffffu, ry, k);
        float rzk = __shfl_sync(0xffffffffu, rz, k);
        float2 kv = *(const float2*)&g_K[(size_t)(base + jk) * DM + h * DH + 2 * lane];
        float pex = fmaf(rxk, w0.x, fmaf(ryk, w1.x, fmaf(rzk, w2.x, bp.x)));
        float pey = fmaf(rxk, w0.y, fmaf(ryk, w1.y, fmaf(rzk, w2.y, bp.y)));
        float s = fmaf(q.x, kv.x + pex, q.y * (kv.y + pey));
#pragma unroll
        for (int off = 16; off; off >>= 1)
            s += __shfl_xor_sync(0xffffffffu, s, off);
        if (lane == k) myscore = s;
    }

    float sc = (lane < KNB) ? myscore : -INFINITY;
    float m = sc;
#pragma unroll
    for (int off = 8; off; off >>= 1)
        m = fmaxf(m, __shfl_xor_sync(0xffffffffu, m, off));
    float e = (lane < KNB) ? __expf(sc - m) : 0.0f;
    float sum = e;
#pragma unroll
    for (int off = 8; off; off >>= 1)
        sum += __shfl_xor_sync(0xffffffffu, sum, off);
    float w = e / sum;

    float2 acc = make_float2(0.f, 0.f);
#pragma unroll
    for (int k = 0; k < KNB; k++) {
        float wk = __shfl_sync(0xffffffffu, w, k);
        int   jk = __shfl_sync(0xffffffffu, j, k);
        float2 v = *(const float2*)&g_V[(size_t)(base + jk) * DM + h * DH + 2 * lane];
        acc.x = fmaf(wk, v.x, acc.x);
        acc.y = fmaf(wk, v.y, acc.y);
    }
    size_t off = (size_t)row * DM + h * DH + 2 * lane;
    __nv_bfloat16 h0 = __float2bfloat16(acc.x);
    __nv_bfloat16 h1 = __float2bfloat16(acc.y);
    __nv_bfloat16 l0 = __float2bfloat16(acc.x - __bfloat162float(h0));
    __nv_bfloat16 l1 = __float2bfloat16(acc.y - __bfloat162float(h1));
    *(uint32_t*)&g_Ahi[off] =
        ((unsigned)__bfloat16_as_ushort(h1) << 16) | __bfloat16_as_ushort(h0);
    *(uint32_t*)&g_Alo[off] =
        ((unsigned)__bfloat16_as_ushort(l1) << 16) | __bfloat16_as_ushort(l0);
}

// ---------------- epilogue: +bo, +residual, LayerNorm ----------------------------
__global__ __launch_bounds__(512) void ln_kernel(const float* __restrict__ feat,
                                                 const float* __restrict__ bo,
                                                 const float* __restrict__ gamma,
                                                 const float* __restrict__ beta,
                                                 float* __restrict__ out) {
    int row = blockIdx.x;
    int tid = threadIdx.x;
    int lane = tid & 31, warp = tid >> 5;
    __shared__ float red[16];
    __shared__ float mu_s, rs_s;

    float x = g_tmp[(size_t)row * DM + tid] + bo[tid] + feat[(size_t)row * DM + tid];

    float s = x;
#pragma unroll
    for (int o = 16; o; o >>= 1) s += __shfl_down_sync(0xffffffffu, s, o);
    if (!lane) red[warp] = s;
    __syncthreads();
    if (tid == 0) {
        float t = 0.0f;
#pragma unroll
        for (int i = 0; i < 16; i++) t += red[i];
        mu_s = t * (1.0f / DM);
    }
    __syncthreads();
    float mu = mu_s;
    float d = x - mu;
    float s2 = d * d;
#pragma unroll
    for (int o = 16; o; o >>= 1) s2 += __shfl_down_sync(0xffffffffu, s2, o);
    if (!lane) red[warp] = s2;
    __syncthreads();
    if (tid == 0) {
        float t = 0.0f;
#pragma unroll
        for (int i = 0; i < 16; i++) t += red[i];
        rs_s = rsqrtf(t * (1.0f / DM) + 1e-5f);
    }
    __syncthreads();
    out[(size_t)row * DM + tid] = d * rs_s * gamma[tid] + beta[tid];
}

// ---------------- launch ---------------------------------------------------------
extern "C" void kernel_launch(void* const* d_in, const int* in_sizes, int n_in,
                              void* d_out, int out_size) {
    const float* pos   = (const float*)d_in[0];
    const float* feat  = (const float*)d_in[1];
    const float* Wq    = (const float*)d_in[3];
    const float* Wk    = (const float*)d_in[4];
    const float* Wv    = (const float*)d_in[5];
    const float* Wo    = (const float*)d_in[6];
    const float* bo    = (const float*)d_in[7];
    const float* Wpos  = (const float*)d_in[8];
    const float* bpos  = (const float*)d_in[9];
    const float* temp  = (const float*)d_in[10];
    const float* gamma = (const float*)d_in[11];
    const float* beta  = (const float*)d_in[12];
    float* out = (float*)d_out;

    float *pQ, *pK, *pV, *pTmp;
    cudaGetSymbolAddress((void**)&pQ,   g_Q);
    cudaGetSymbolAddress((void**)&pK,   g_K);
    cudaGetSymbolAddress((void**)&pV,   g_V);
    cudaGetSymbolAddress((void**)&pTmp, g_tmp);

    cudaFuncSetAttribute(fused_qkv_knn, cudaFuncAttributeMaxDynamicSharedMemorySize, GEMM_SMEM);
    cudaFuncSetAttribute(gemm_o_tc,     cudaFuncAttributeMaxDynamicSharedMemorySize, GEMM_SMEM);

    prep_kernel<<<4096 + 1024 + 32, 256>>>(feat, pos, Wq, Wk, Wv, Wo);

    fused_qkv_knn<<<1792, 256, GEMM_SMEM>>>(pQ, pK, pV);

    attn_kernel<<<ROWS * NH * 32 / 256, 256>>>(pos, Wpos, bpos, temp);

    gemm_o_tc<<<dim3(DM / 128, ROWS / 128), 256, GEMM_SMEM>>>(pTmp);

    ln_kernel<<<ROWS, 512>>>(feat, bo, gamma, beta, out);
}

// round 9
// speedup vs baseline: 1.0044x; 1.0044x over previous
#include <cuda_runtime.h>
#include <cuda_bf16.h>
#include <math.h>
#include <stdint.h>

#define BATCH 2
#define NPTS 4096
#define DM 512
#define NH 8
#define DH 64
#define KNB 16
#define ROWS (BATCH * NPTS)   // 8192

// ---------------- scratch (device globals; no allocation allowed) ----------------
__device__ float g_Q[ROWS * DM];
__device__ float g_K[ROWS * DM];
__device__ float g_V[ROWS * DM];
__device__ float g_tmp[ROWS * DM];
__device__ int   g_idx[ROWS * KNB];
__device__ float4 g_pos4[ROWS];                 // padded positions (x,y,z,0)
__device__ __nv_bfloat16 g_Ahi[ROWS * DM];      // activation split (feat, later att)
__device__ __nv_bfloat16 g_Alo[ROWS * DM];
__device__ __nv_bfloat16 g_Bhi[4 * DM * DM];    // transposed weight split [z][n*DM+k]
__device__ __nv_bfloat16 g_Blo[4 * DM * DM];

// ---------------- helpers --------------------------------------------------------
__device__ __forceinline__ uint32_t smem_u32(const void* p) {
    uint32_t a;
    asm("{ .reg .u64 t; cvta.to.shared.u64 t, %1; cvt.u32.u64 %0, t; }"
        : "=r"(a) : "l"(p));
    return a;
}
#define CP16(dst, src) \
    asm volatile("cp.async.cg.shared.global [%0], [%1], 16;" :: "r"(dst), "l"(src))
#define CP_COMMIT() asm volatile("cp.async.commit_group;" ::: "memory")
#define CP_WAIT(n)  asm volatile("cp.async.wait_group %0;" :: "n"(n) : "memory")

__device__ __forceinline__ void ldmx4(uint32_t* r, uint32_t addr) {
    asm volatile("ldmatrix.sync.aligned.m8n8.x4.shared.b16 {%0,%1,%2,%3}, [%4];"
                 : "=r"(r[0]), "=r"(r[1]), "=r"(r[2]), "=r"(r[3]) : "r"(addr));
}
__device__ __forceinline__ void mma16816(float* c, const uint32_t* a, const uint32_t* b) {
    asm volatile(
        "mma.sync.aligned.m16n8k16.row.col.f32.bf16.bf16.f32 "
        "{%0,%1,%2,%3}, {%4,%5,%6,%7}, {%8,%9}, {%0,%1,%2,%3};"
        : "+f"(c[0]), "+f"(c[1]), "+f"(c[2]), "+f"(c[3])
        : "r"(a[0]), "r"(a[1]), "r"(a[2]), "r"(a[3]), "r"(b[0]), "r"(b[1]));
}

// ---------------- prep: split feat + transpose/split weights + pos4 --------------
__global__ __launch_bounds__(256) void prep_kernel(const float* __restrict__ feat,
                                                   const float* __restrict__ pos,
                                                   const float* __restrict__ W0,
                                                   const float* __restrict__ W1,
                                                   const float* __restrict__ W2,
                                                   const float* __restrict__ W3) {
    __shared__ float t[32][33];
    if (blockIdx.x < 4096) {                      // split feat
        int i = blockIdx.x * blockDim.x + threadIdx.x;
        float4 v = *(const float4*)&feat[(size_t)i * 4];
        __nv_bfloat16 h0 = __float2bfloat16(v.x), h1 = __float2bfloat16(v.y);
        __nv_bfloat16 h2 = __float2bfloat16(v.z), h3 = __float2bfloat16(v.w);
        __nv_bfloat16 l0 = __float2bfloat16(v.x - __bfloat162float(h0));
        __nv_bfloat16 l1 = __float2bfloat16(v.y - __bfloat162float(h1));
        __nv_bfloat16 l2 = __float2bfloat16(v.z - __bfloat162float(h2));
        __nv_bfloat16 l3 = __float2bfloat16(v.w - __bfloat162float(h3));
        uint2 h, l;
        h.x = ((unsigned)__bfloat16_as_ushort(h1) << 16) | __bfloat16_as_ushort(h0);
        h.y = ((unsigned)__bfloat16_as_ushort(h3) << 16) | __bfloat16_as_ushort(h2);
        l.x = ((unsigned)__bfloat16_as_ushort(l1) << 16) | __bfloat16_as_ushort(l0);
        l.y = ((unsigned)__bfloat16_as_ushort(l3) << 16) | __bfloat16_as_ushort(l2);
        *(uint2*)&g_Ahi[(size_t)i * 4] = h;
        *(uint2*)&g_Alo[(size_t)i * 4] = l;
    } else if (blockIdx.x < 4096 + 1024) {        // transpose+split weights
        int id = blockIdx.x - 4096;               // 16 x 16 x 4
        int z = id >> 8;
        int by = ((id >> 4) & 15) * 32, bx = (id & 15) * 32;
        const float* src = (z == 0) ? W0 : (z == 1) ? W1 : (z == 2) ? W2 : W3;
        size_t zoff = (size_t)z * DM * DM;
        int tx = threadIdx.x & 31, ty = threadIdx.x >> 5;   // 32 x 8
#pragma unroll
        for (int i = 0; i < 32; i += 8)
            t[ty + i][tx] = src[(size_t)(by + ty + i) * DM + bx + tx];
        __syncthreads();
#pragma unroll
        for (int i = 0; i < 32; i += 8) {
            float v = t[tx][ty + i];
            __nv_bfloat16 h = __float2bfloat16(v);
            __nv_bfloat16 l = __float2bfloat16(v - __bfloat162float(h));
            size_t o = zoff + (size_t)(bx + ty + i) * DM + by + tx;
            g_Bhi[o] = h;
            g_Blo[o] = l;
        }
    } else {                                      // pos -> float4 (32 CTAs)
        int i = (blockIdx.x - 4096 - 1024) * blockDim.x + threadIdx.x;  // 0..8191
        g_pos4[i] = make_float4(pos[i * 3 + 0], pos[i * 3 + 1], pos[i * 3 + 2], 0.0f);
    }
}

// ---------------- HMMA bf16x3 GEMM body ------------------------------------------
// Stage layout (conflict-free LDSM): per stage 32 KB.
//   A region [0, 16384): 128 rows x 128B. Row r chunks 0-3 = A_hi k-halves,
//     chunks 4-7 = A_lo; physical chunk = logical ^ (r & 7).
//   B region [16384, 32768): same for B rows (N dimension).
// 8 consecutive rows of an ldmatrix read hit 8 distinct 16B chunks -> 32 banks.
#define BKC 32
#define NCH (DM / BKC)        // 16
#define ST_A 0
#define ST_B 16384
#define STAGE 32768
#define NSTG 3
#define GEMM_SMEM (NSTG * STAGE)   // 98304

__device__ __forceinline__ void stage_load(uint32_t sb, int slot, int koff, int tid,
                                           const __nv_bfloat16* __restrict__ Ahi,
                                           const __nv_bfloat16* __restrict__ Alo,
                                           const __nv_bfloat16* __restrict__ Bhi,
                                           const __nv_bfloat16* __restrict__ Blo,
                                           int bm, int bn) {
    uint32_t stg = sb + (uint32_t)slot * STAGE;
#pragma unroll
    for (int i = 0; i < 8; i++) {
        int v = i * 256 + tid;          // 0..2047 ; arr resolved per unrolled i
        int arr = v >> 9;               // 0:Ahi 1:Alo 2:Bhi 3:Blo
        int idx = v & 511;
        int r = idx >> 2, c = idx & 3;
        const __nv_bfloat16* g = (arr == 0) ? Ahi : (arr == 1) ? Alo
                               : (arr == 2) ? Bhi : Blo;
        int rowbase = (arr < 2) ? bm : bn;
        uint32_t region = (arr < 2) ? ST_A : ST_B;
        int logical = (arr & 1) ? (c + 4) : c;
        uint32_t dst = stg + region + (uint32_t)(r * 128 + ((logical ^ (r & 7)) << 4));
        CP16(dst, &g[(size_t)(rowbase + r) * DM + koff + c * 8]);
    }
    CP_COMMIT();
}

__device__ __forceinline__ void tc_gemm_body(char* smem,
                                             const __nv_bfloat16* __restrict__ Ahi,
                                             const __nv_bfloat16* __restrict__ Alo,
                                             const __nv_bfloat16* __restrict__ Bhi,
                                             const __nv_bfloat16* __restrict__ Blo,
                                             float* __restrict__ C,
                                             int bm, int bn) {
    uint32_t sb = smem_u32(smem);
    int tid = threadIdx.x;             // 256
    int wid = tid >> 5, lane = tid & 31;
    int warp_m = wid & 3, warp_n = wid >> 2;       // 4 x 2 warps -> 32x64 warp tile

    float c[2][8][4];
#pragma unroll
    for (int mt = 0; mt < 2; mt++)
#pragma unroll
        for (int nt = 0; nt < 8; nt++)
#pragma unroll
            for (int e = 0; e < 4; e++) c[mt][nt][e] = 0.0f;

    int arow = warp_m * 32 + (lane & 15);
    int akh  = lane >> 4;
    int axor = arow & 7;
    int brow = warp_n * 64 + (lane & 7) + ((lane >> 4) << 3);
    int bkh  = (lane >> 3) & 1;
    int bxor = brow & 7;

    // prologue: stages 0, 1
    stage_load(sb, 0, 0,   tid, Ahi, Alo, Bhi, Blo, bm, bn);
    stage_load(sb, 1, BKC, tid, Ahi, Alo, Bhi, Blo, bm, bn);

    for (int kc = 0; kc < NCH; kc++) {
        if (kc == NCH - 1) { CP_WAIT(0); } else { CP_WAIT(1); }
        __syncthreads();   // stage kc ready; all warps done with stage kc-1 slot
        if (kc + 2 < NCH)
            stage_load(sb, (kc + 2) % NSTG, (kc + 2) * BKC, tid,
                       Ahi, Alo, Bhi, Blo, bm, bn);

        uint32_t stg = sb + (uint32_t)(kc % NSTG) * STAGE;
#pragma unroll
        for (int ks = 0; ks < 2; ks++) {
            uint32_t ah[2][4], al[2][4];
#pragma unroll
            for (int mt = 0; mt < 2; mt++) {
                uint32_t rbase = stg + ST_A + (uint32_t)((arow + mt * 16) * 128);
                ldmx4(ah[mt], rbase + (uint32_t)((((ks * 2 + akh)    ) ^ axor) << 4));
                ldmx4(al[mt], rbase + (uint32_t)((((ks * 2 + akh) + 4) ^ axor) << 4));
            }
#pragma unroll
            for (int np = 0; np < 4; np++) {
                uint32_t rbase = stg + ST_B + (uint32_t)((brow + np * 16) * 128);
                uint32_t bh[4], bl[4];
                ldmx4(bh, rbase + (uint32_t)((((ks * 2 + bkh)    ) ^ bxor) << 4));
                ldmx4(bl, rbase + (uint32_t)((((ks * 2 + bkh) + 4) ^ bxor) << 4));
#pragma unroll
                for (int mt = 0; mt < 2; mt++) {
                    mma16816(c[mt][np * 2 + 0], ah[mt], &bh[0]);
                    mma16816(c[mt][np * 2 + 1], ah[mt], &bh[2]);
                    mma16816(c[mt][np * 2 + 0], ah[mt], &bl[0]);
                    mma16816(c[mt][np * 2 + 1], ah[mt], &bl[2]);
                    mma16816(c[mt][np * 2 + 0], al[mt], &bh[0]);
                    mma16816(c[mt][np * 2 + 1], al[mt], &bh[2]);
                }
            }
        }
        __syncthreads();   // all warps done reading stage kc before its slot refills
    }

    int gid = lane >> 2, t4 = lane & 3;
#pragma unroll
    for (int mt = 0; mt < 2; mt++) {
        int r = bm + warp_m * 32 + mt * 16 + gid;
#pragma unroll
        for (int nt = 0; nt < 8; nt++) {
            int col = bn + warp_n * 64 + nt * 8 + t4 * 2;
            *(float2*)&C[(size_t)r * DM + col] =
                make_float2(c[mt][nt][0], c[mt][nt][1]);
            *(float2*)&C[(size_t)(r + 8) * DM + col] =
                make_float2(c[mt][nt][2], c[mt][nt][3]);
        }
    }
}

// ---------------- fused: QKV GEMMs + kNN, interleaved CTA groups -----------------
#define QW 8
__global__ __launch_bounds__(256, 2) void fused_qkv_knn(float* __restrict__ Cq,
                                                        float* __restrict__ Ck,
                                                        float* __restrict__ Cv) {
    extern __shared__ __align__(128) char smem[];
    int g7 = blockIdx.x / 7, r7 = blockIdx.x % 7;

    if (r7 < 3) {
        // ---- GEMM CTA ----
        int id = g7 * 3 + r7;              // 0..767
        int z  = id >> 8;                  // 0..2
        int rem = id & 255;
        int bm = (rem >> 2) * 128, bn = (rem & 3) * 128;
        float* C = (z == 0) ? Cq : (z == 1) ? Ck : Cv;
        tc_gemm_body(smem, g_Ahi, g_Alo,
                     g_Bhi + (size_t)z * DM * DM, g_Blo + (size_t)z * DM * DM,
                     C, bm, bn);
    } else {
        // ---- kNN CTA: warp per query, global-threshold pruned top-17 ----
        unsigned long long (*smrg)[32][KNB + 2] =
            (unsigned long long (*)[32][KNB + 2])smem;
        int warp = threadIdx.x >> 5, lane = threadIdx.x & 31;
        int q = (g7 * 4 + (r7 - 3)) * QW + warp;    // 0..8191
        int b = q >> 12;
        int base = b << 12;
        float4 qp = g_pos4[q];

        unsigned long long key[KNB + 1];
#pragma unroll
        for (int i = 0; i < KNB + 1; i++) key[i] = 0xFFFFFFFFFFFFFFFFull;
        unsigned long long Tb = 0xFFFFFFFFFFFFFFFFull;

        for (int step = 0; step < NPTS / 32; step++) {
            if ((step & 7) == 0) {
                unsigned long long w = key[KNB];
#pragma unroll
                for (int off = 16; off; off >>= 1) {
                    unsigned long long o = __shfl_xor_sync(0xffffffffu, w, off);
                    if (o < w) w = o;
                }
                Tb = w;
            }
            int j = step * 32 + lane;
            float4 p = g_pos4[base + j];
            float dx = qp.x - p.x;
            float dy = qp.y - p.y;
            float dz = qp.z - p.z;
            float d = fmaf(dx, dx, fmaf(dy, dy, dz * dz));
            unsigned long long kk =
                ((unsigned long long)__float_as_uint(d) << 32) | (unsigned)j;
            if (kk < Tb) {
#pragma unroll
                for (int p2 = KNB; p2 >= 1; p2--) {
                    unsigned long long lower = key[p2 - 1];
                    unsigned long long cur   = key[p2];
                    key[p2] = (kk >= cur) ? cur : ((kk >= lower) ? kk : lower);
                }
                key[0] = (kk < key[0]) ? kk : key[0];
            }
        }

#pragma unroll
        for (int i = 0; i < KNB + 1; i++) smrg[warp][lane][i] = key[i];
        smrg[warp][lane][KNB + 1] = 0xFFFFFFFFFFFFFFFFull;
        __syncwarp();

        int p = 0;
        unsigned long long head = smrg[warp][lane][0];
        for (int out = 0; out < KNB + 1; out++) {
            unsigned long long m = head;
#pragma unroll
            for (int off = 16; off; off >>= 1) {
                unsigned long long o = __shfl_xor_sync(0xffffffffu, m, off);
                if (o < m) m = o;
            }
            if (out > 0 && lane == 0)
                g_idx[q * KNB + out - 1] = (int)(unsigned)m;
            if (head == m) { p++; head = smrg[warp][lane][p]; }
        }
    }
}

__global__ __launch_bounds__(256, 2) void gemm_o_tc(float* __restrict__ C) {
    extern __shared__ __align__(128) char smem[];
    tc_gemm_body(smem, g_Ahi, g_Alo,
                 g_Bhi + (size_t)3 * DM * DM, g_Blo + (size_t)3 * DM * DM,
                 C, blockIdx.y * 128, blockIdx.x * 128);
}

// ---------------- attention: warp per (row, head); writes bf16 hi/lo splits -----
__global__ __launch_bounds__(256) void attn_kernel(const float* __restrict__ pos,
                                                   const float* __restrict__ Wpos,
                                                   const float* __restrict__ bpos,
                                                   const float* __restrict__ temp) {
    int gw   = (blockIdx.x * blockDim.x + threadIdx.x) >> 5;
    int lane = threadIdx.x & 31;
    int row  = gw >> 3;
    int h    = gw & 7;
    int b    = row >> 12;
    int n    = row & (NPTS - 1);
    const float* posb = pos + (size_t)b * NPTS * 3;
    int base = (b << 12);

    int j = 0;
    float rx = 0.f, ry = 0.f, rz = 0.f;
    float px = posb[n * 3 + 0], py = posb[n * 3 + 1], pz = posb[n * 3 + 2];
    if (lane < KNB) {
        j  = g_idx[row * KNB + lane];
        rx = px - posb[j * 3 + 0];
        ry = py - posb[j * 3 + 1];
        rz = pz - posb[j * 3 + 2];
    }

    float invT = 1.0f / temp[0];
    float2 q = *(const float2*)&g_Q[(size_t)row * DM + h * DH + 2 * lane];
    q.x *= invT; q.y *= invT;
    float2 w0 = *(const float2*)&Wpos[0 * 128 + 2 * lane];
    float2 w1 = *(const float2*)&Wpos[1 * 128 + 2 * lane];
    float2 w2 = *(const float2*)&Wpos[2 * 128 + 2 * lane];
    float2 bp = *(const float2*)&bpos[2 * lane];

    float myscore = 0.0f;
#pragma unroll
    for (int k = 0; k < KNB; k++) {
        int   jk  = __shfl_sync(0xffffffffu, j,  k);
        float rxk = __shfl_sync(0xffffffffu, rx, k);
        float ryk = __shfl_sync(0xffffffffu, ry, k);
        float rzk = __shfl_sync(0xffffffffu, rz, k);
        float2 kv = *(const float2*)&g_K[(size_t)(base + jk) * DM + h * DH + 2 * lane];
        float pex = fmaf(rxk, w0.x, fmaf(ryk, w1.x, fmaf(rzk, w2.x, bp.x)));
        float pey = fmaf(rxk, w0.y, fmaf(ryk, w1.y, fmaf(rzk, w2.y, bp.y)));
        float s = fmaf(q.x, kv.x + pex, q.y * (kv.y + pey));
#pragma unroll
        for (int off = 16; off; off >>= 1)
            s += __shfl_xor_sync(0xffffffffu, s, off);
        if (lane == k) myscore = s;
    }

    float sc = (lane < KNB) ? myscore : -INFINITY;
    float m = sc;
#pragma unroll
    for (int off = 8; off; off >>= 1)
        m = fmaxf(m, __shfl_xor_sync(0xffffffffu, m, off));
    float e = (lane < KNB) ? __expf(sc - m) : 0.0f;
    float sum = e;
#pragma unroll
    for (int off = 8; off; off >>= 1)
        sum += __shfl_xor_sync(0xffffffffu, sum, off);
    float w = e / sum;

    float2 acc = make_float2(0.f, 0.f);
#pragma unroll
    for (int k = 0; k < KNB; k++) {
        float wk = __shfl_sync(0xffffffffu, w, k);
        int   jk = __shfl_sync(0xffffffffu, j, k);
        float2 v = *(const float2*)&g_V[(size_t)(base + jk) * DM + h * DH + 2 * lane];
        acc.x = fmaf(wk, v.x, acc.x);
        acc.y = fmaf(wk, v.y, acc.y);
    }
    size_t off = (size_t)row * DM + h * DH + 2 * lane;
    __nv_bfloat16 h0 = __float2bfloat16(acc.x);
    __nv_bfloat16 h1 = __float2bfloat16(acc.y);
    __nv_bfloat16 l0 = __float2bfloat16(acc.x - __bfloat162float(h0));
    __nv_bfloat16 l1 = __float2bfloat16(acc.y - __bfloat162float(h1));
    *(uint32_t*)&g_Ahi[off] =
        ((unsigned)__bfloat16_as_ushort(h1) << 16) | __bfloat16_as_ushort(h0);
    *(uint32_t*)&g_Alo[off] =
        ((unsigned)__bfloat16_as_ushort(l1) << 16) | __bfloat16_as_ushort(l0);
}

// ---------------- epilogue: +bo, +residual, LayerNorm ----------------------------
__global__ __launch_bounds__(512) void ln_kernel(const float* __restrict__ feat,
                                                 const float* __restrict__ bo,
                                                 const float* __restrict__ gamma,
                                                 const float* __restrict__ beta,
                                                 float* __restrict__ out) {
    int row = blockIdx.x;
    int tid = threadIdx.x;
    int lane = tid & 31, warp = tid >> 5;
    __shared__ float red[16];
    __shared__ float mu_s, rs_s;

    float x = g_tmp[(size_t)row * DM + tid] + bo[tid] + feat[(size_t)row * DM + tid];

    float s = x;
#pragma unroll
    for (int o = 16; o; o >>= 1) s += __shfl_down_sync(0xffffffffu, s, o);
    if (!lane) red[warp] = s;
    __syncthreads();
    if (tid == 0) {
        float t = 0.0f;
#pragma unroll
        for (int i = 0; i < 16; i++) t += red[i];
        mu_s = t * (1.0f / DM);
    }
    __syncthreads();
    float mu = mu_s;
    float d = x - mu;
    float s2 = d * d;
#pragma unroll
    for (int o = 16; o; o >>= 1) s2 += __shfl_down_sync(0xffffffffu, s2, o);
    if (!lane) red[warp] = s2;
    __syncthreads();
    if (tid == 0) {
        float t = 0.0f;
#pragma unroll
        for (int i = 0; i < 16; i++) t += red[i];
        rs_s = rsqrtf(t * (1.0f / DM) + 1e-5f);
    }
    __syncthreads();
    out[(size_t)row * DM + tid] = d * rs_s * gamma[tid] + beta[tid];
}

// ---------------- launch ---------------------------------------------------------
extern "C" void kernel_launch(void* const* d_in, const int* in_sizes, int n_in,
                              void* d_out, int out_size) {
    const float* pos   = (const float*)d_in[0];
    const float* feat  = (const float*)d_in[1];
    const float* Wq    = (const float*)d_in[3];
    const float* Wk    = (const float*)d_in[4];
    const float* Wv    = (const float*)d_in[5];
    const float* Wo    = (const float*)d_in[6];
    const float* bo    = (const float*)d_in[7];
    const float* Wpos  = (const float*)d_in[8];
    const float* bpos  = (const float*)d_in[9];
    const float* temp  = (const float*)d_in[10];
    const float* gamma = (const float*)d_in[11];
    const float* beta  = (const float*)d_in[12];
    float* out = (float*)d_out;

    float *pQ, *pK, *pV, *pTmp;
    cudaGetSymbolAddress((void**)&pQ,   g_Q);
    cudaGetSymbolAddress((void**)&pK,   g_K);
    cudaGetSymbolAddress((void**)&pV,   g_V);
    cudaGetSymbolAddress((void**)&pTmp, g_tmp);

    cudaFuncSetAttribute(fused_qkv_knn, cudaFuncAttributeMaxDynamicSharedMemorySize, GEMM_SMEM);
    cudaFuncSetAttribute(gemm_o_tc,     cudaFuncAttributeMaxDynamicSharedMemorySize, GEMM_SMEM);

    prep_kernel<<<4096 + 1024 + 32, 256>>>(feat, pos, Wq, Wk, Wv, Wo);

    fused_qkv_knn<<<1792, 256, GEMM_SMEM>>>(pQ, pK, pV);

    attn_kernel<<<ROWS * NH * 32 / 256, 256>>>(pos, Wpos, bpos, temp);

    gemm_o_tc<<<dim3(DM / 128, ROWS / 128), 256, GEMM_SMEM>>>(pTmp);

    ln_kernel<<<ROWS, 512>>>(feat, bo, gamma, beta, out);
}

// round 10
// speedup vs baseline: 1.1297x; 1.1247x over previous
#include <cuda_runtime.h>
#include <cuda_fp16.h>
#include <math.h>
#include <stdint.h>

#define BATCH 2
#define NPTS 4096
#define DM 512
#define NH 8
#define DH 64
#define KNB 16
#define ROWS (BATCH * NPTS)   // 8192

// ---------------- scratch (device globals; no allocation allowed) ----------------
__device__ float g_Q[ROWS * DM];
__device__ float g_K[ROWS * DM];
__device__ float g_V[ROWS * DM];
__device__ float g_tmp[ROWS * DM];
__device__ int   g_idx[ROWS * KNB];
__device__ float4 g_pos4[ROWS];               // padded positions (x,y,z,0)
__device__ __half g_Ahi[ROWS * DM];           // activation fp16 hi (feat, later att)
__device__ __half g_Alo[ROWS * DM];           // activation fp16 lo
__device__ __half g_Bh[4 * DM * DM];          // transposed weights, single fp16

// ---------------- helpers --------------------------------------------------------
__device__ __forceinline__ uint32_t smem_u32(const void* p) {
    uint32_t a;
    asm("{ .reg .u64 t; cvta.to.shared.u64 t, %1; cvt.u32.u64 %0, t; }"
        : "=r"(a) : "l"(p));
    return a;
}
#define CP16(dst, src) \
    asm volatile("cp.async.cg.shared.global [%0], [%1], 16;" :: "r"(dst), "l"(src))
#define CP_COMMIT() asm volatile("cp.async.commit_group;" ::: "memory")
#define CP_WAIT(n)  asm volatile("cp.async.wait_group %0;" :: "n"(n) : "memory")

__device__ __forceinline__ void ldmx4(uint32_t* r, uint32_t addr) {
    asm volatile("ldmatrix.sync.aligned.m8n8.x4.shared.b16 {%0,%1,%2,%3}, [%4];"
                 : "=r"(r[0]), "=r"(r[1]), "=r"(r[2]), "=r"(r[3]) : "r"(addr));
}
__device__ __forceinline__ void mma16816(float* c, const uint32_t* a, const uint32_t* b) {
    asm volatile(
        "mma.sync.aligned.m16n8k16.row.col.f32.f16.f16.f32 "
        "{%0,%1,%2,%3}, {%4,%5,%6,%7}, {%8,%9}, {%0,%1,%2,%3};"
        : "+f"(c[0]), "+f"(c[1]), "+f"(c[2]), "+f"(c[3])
        : "r"(a[0]), "r"(a[1]), "r"(a[2]), "r"(a[3]), "r"(b[0]), "r"(b[1]));
}
__device__ __forceinline__ uint32_t pkh(__half a, __half b) {
    return ((uint32_t)__half_as_ushort(b) << 16) | __half_as_ushort(a);
}

// ---------------- prep: split feat (fp16 hi/lo) + transpose weights + pos4 -------
__global__ __launch_bounds__(256) void prep_kernel(const float* __restrict__ feat,
                                                   const float* __restrict__ pos,
                                                   const float* __restrict__ W0,
                                                   const float* __restrict__ W1,
                                                   const float* __restrict__ W2,
                                                   const float* __restrict__ W3) {
    __shared__ float t[32][33];
    if (blockIdx.x < 4096) {                      // split feat
        int i = blockIdx.x * blockDim.x + threadIdx.x;
        float4 v = *(const float4*)&feat[(size_t)i * 4];
        __half h0 = __float2half(v.x), h1 = __float2half(v.y);
        __half h2 = __float2half(v.z), h3 = __float2half(v.w);
        __half l0 = __float2half(v.x - __half2float(h0));
        __half l1 = __float2half(v.y - __half2float(h1));
        __half l2 = __float2half(v.z - __half2float(h2));
        __half l3 = __float2half(v.w - __half2float(h3));
        uint2 h, l;
        h.x = pkh(h0, h1); h.y = pkh(h2, h3);
        l.x = pkh(l0, l1); l.y = pkh(l2, l3);
        *(uint2*)&g_Ahi[(size_t)i * 4] = h;
        *(uint2*)&g_Alo[(size_t)i * 4] = l;
    } else if (blockIdx.x < 4096 + 1024) {        // transpose weights -> fp16
        int id = blockIdx.x - 4096;               // 16 x 16 x 4
        int z = id >> 8;
        int by = ((id >> 4) & 15) * 32, bx = (id & 15) * 32;
        const float* src = (z == 0) ? W0 : (z == 1) ? W1 : (z == 2) ? W2 : W3;
        size_t zoff = (size_t)z * DM * DM;
        int tx = threadIdx.x & 31, ty = threadIdx.x >> 5;   // 32 x 8
#pragma unroll
        for (int i = 0; i < 32; i += 8)
            t[ty + i][tx] = src[(size_t)(by + ty + i) * DM + bx + tx];
        __syncthreads();
#pragma unroll
        for (int i = 0; i < 32; i += 8)
            g_Bh[zoff + (size_t)(bx + ty + i) * DM + by + tx] =
                __float2half(t[tx][ty + i]);
    } else {                                      // pos -> float4 (32 CTAs)
        int i = (blockIdx.x - 4096 - 1024) * blockDim.x + threadIdx.x;  // 0..8191
        g_pos4[i] = make_float4(pos[i * 3 + 0], pos[i * 3 + 1], pos[i * 3 + 2], 0.0f);
    }
}

// ---------------- HMMA fp16 2-term GEMM body -------------------------------------
// C = (Ahi + Alo) * Bh^T.  Stage 32KB:
//   A region [0,16K): 128 rows x 128B; chunks 0-3 = A_hi k-halves, 4-7 = A_lo;
//     physical chunk = logical ^ (r & 7)  -> LDSM conflict-free.
//   B region [16K,32K): 128 rows x 128B; logical chunks 0-3 (k-halves),
//     physical = logical ^ (r & 7).
#define BKC 32
#define NCH (DM / BKC)        // 16
#define ST_A 0
#define ST_B 16384
#define STAGE 32768
#define NSTG 3
#define GEMM_SMEM (NSTG * STAGE)   // 98304

__device__ __forceinline__ void stage_load(uint32_t sb, int slot, int koff, int tid,
                                           const __half* __restrict__ Ahi,
                                           const __half* __restrict__ Alo,
                                           const __half* __restrict__ Bh,
                                           int bm, int bn) {
    uint32_t stg = sb + (uint32_t)slot * STAGE;
#pragma unroll
    for (int i = 0; i < 6; i++) {
        int v = i * 256 + tid;          // 0..1535
        int arr = v >> 9;               // 0:Ahi 1:Alo 2:Bh
        int idx = v & 511;
        int r = idx >> 2, c = idx & 3;
        const __half* g = (arr == 0) ? Ahi : (arr == 1) ? Alo : Bh;
        int rowbase = (arr < 2) ? bm : bn;
        uint32_t region = (arr < 2) ? ST_A : ST_B;
        int logical = (arr == 1) ? (c + 4) : c;
        uint32_t dst = stg + region + (uint32_t)(r * 128 + ((logical ^ (r & 7)) << 4));
        CP16(dst, &g[(size_t)(rowbase + r) * DM + koff + c * 8]);
    }
    CP_COMMIT();
}

__device__ __forceinline__ void tc_gemm_body(char* smem,
                                             const __half* __restrict__ Ahi,
                                             const __half* __restrict__ Alo,
                                             const __half* __restrict__ Bh,
                                             float* __restrict__ C,
                                             int bm, int bn) {
    uint32_t sb = smem_u32(smem);
    int tid = threadIdx.x;             // 256
    int wid = tid >> 5, lane = tid & 31;
    int warp_m = wid & 3, warp_n = wid >> 2;       // 4 x 2 warps -> 32x64 warp tile

    float c[2][8][4];
#pragma unroll
    for (int mt = 0; mt < 2; mt++)
#pragma unroll
        for (int nt = 0; nt < 8; nt++)
#pragma unroll
            for (int e = 0; e < 4; e++) c[mt][nt][e] = 0.0f;

    int arow = warp_m * 32 + (lane & 15);
    int akh  = lane >> 4;
    int axor = arow & 7;
    int brow = warp_n * 64 + (lane & 7) + ((lane >> 4) << 3);
    int bkh  = (lane >> 3) & 1;
    int bxor = brow & 7;

    stage_load(sb, 0, 0,   tid, Ahi, Alo, Bh, bm, bn);
    stage_load(sb, 1, BKC, tid, Ahi, Alo, Bh, bm, bn);

    for (int kc = 0; kc < NCH; kc++) {
        if (kc == NCH - 1) { CP_WAIT(0); } else { CP_WAIT(1); }
        __syncthreads();
        if (kc + 2 < NCH)
            stage_load(sb, (kc + 2) % NSTG, (kc + 2) * BKC, tid, Ahi, Alo, Bh, bm, bn);

        uint32_t stg = sb + (uint32_t)(kc % NSTG) * STAGE;
#pragma unroll
        for (int ks = 0; ks < 2; ks++) {
            uint32_t ah[2][4], al[2][4];
#pragma unroll
            for (int mt = 0; mt < 2; mt++) {
                uint32_t rbase = stg + ST_A + (uint32_t)((arow + mt * 16) * 128);
                ldmx4(ah[mt], rbase + (uint32_t)((((ks * 2 + akh)    ) ^ axor) << 4));
                ldmx4(al[mt], rbase + (uint32_t)((((ks * 2 + akh) + 4) ^ axor) << 4));
            }
#pragma unroll
            for (int np = 0; np < 4; np++) {
                uint32_t rbase = stg + ST_B + (uint32_t)((brow + np * 16) * 128);
                uint32_t bh[4];
                ldmx4(bh, rbase + (uint32_t)(((ks * 2 + bkh) ^ bxor) << 4));
#pragma unroll
                for (int mt = 0; mt < 2; mt++) {
                    mma16816(c[mt][np * 2 + 0], ah[mt], &bh[0]);
                    mma16816(c[mt][np * 2 + 1], ah[mt], &bh[2]);
                    mma16816(c[mt][np * 2 + 0], al[mt], &bh[0]);
                    mma16816(c[mt][np * 2 + 1], al[mt], &bh[2]);
                }
            }
        }
        __syncthreads();
    }

    int gid = lane >> 2, t4 = lane & 3;
#pragma unroll
    for (int mt = 0; mt < 2; mt++) {
        int r = bm + warp_m * 32 + mt * 16 + gid;
#pragma unroll
        for (int nt = 0; nt < 8; nt++) {
            int col = bn + warp_n * 64 + nt * 8 + t4 * 2;
            *(float2*)&C[(size_t)r * DM + col] =
                make_float2(c[mt][nt][0], c[mt][nt][1]);
            *(float2*)&C[(size_t)(r + 8) * DM + col] =
                make_float2(c[mt][nt][2], c[mt][nt][3]);
        }
    }
}

// ---------------- fused: QKV GEMMs + kNN, interleaved CTA groups -----------------
#define QW 8
__global__ __launch_bounds__(256, 2) void fused_qkv_knn(float* __restrict__ Cq,
                                                        float* __restrict__ Ck,
                                                        float* __restrict__ Cv) {
    extern __shared__ __align__(128) char smem[];
    int g7 = blockIdx.x / 7, r7 = blockIdx.x % 7;

    if (r7 < 3) {
        int id = g7 * 3 + r7;              // 0..767
        int z  = id >> 8;
        int rem = id & 255;
        int bm = (rem >> 2) * 128, bn = (rem & 3) * 128;
        float* C = (z == 0) ? Cq : (z == 1) ? Ck : Cv;
        tc_gemm_body(smem, g_Ahi, g_Alo, g_Bh + (size_t)z * DM * DM, C, bm, bn);
    } else {
        // ---- kNN CTA: warp per query, global-threshold pruned top-17 ----
        unsigned long long (*smrg)[32][KNB + 2] =
            (unsigned long long (*)[32][KNB + 2])smem;
        int warp = threadIdx.x >> 5, lane = threadIdx.x & 31;
        int q = (g7 * 4 + (r7 - 3)) * QW + warp;    // 0..8191
        int b = q >> 12;
        int base = b << 12;
        float4 qp = g_pos4[q];

        unsigned long long key[KNB + 1];
#pragma unroll
        for (int i = 0; i < KNB + 1; i++) key[i] = 0xFFFFFFFFFFFFFFFFull;
        unsigned long long Tb = 0xFFFFFFFFFFFFFFFFull;

        for (int step = 0; step < NPTS / 32; step++) {
            if ((step & 7) == 0) {
                unsigned long long w = key[KNB];
#pragma unroll
                for (int off = 16; off; off >>= 1) {
                    unsigned long long o = __shfl_xor_sync(0xffffffffu, w, off);
                    if (o < w) w = o;
                }
                Tb = w;
            }
            int j = step * 32 + lane;
            float4 p = g_pos4[base + j];
            float dx = qp.x - p.x;
            float dy = qp.y - p.y;
            float dz = qp.z - p.z;
            float d = fmaf(dx, dx, fmaf(dy, dy, dz * dz));
            unsigned long long kk =
                ((unsigned long long)__float_as_uint(d) << 32) | (unsigned)j;
            if (kk < Tb) {
#pragma unroll
                for (int p2 = KNB; p2 >= 1; p2--) {
                    unsigned long long lower = key[p2 - 1];
                    unsigned long long cur   = key[p2];
                    key[p2] = (kk >= cur) ? cur : ((kk >= lower) ? kk : lower);
                }
                key[0] = (kk < key[0]) ? kk : key[0];
            }
        }

#pragma unroll
        for (int i = 0; i < KNB + 1; i++) smrg[warp][lane][i] = key[i];
        smrg[warp][lane][KNB + 1] = 0xFFFFFFFFFFFFFFFFull;
        __syncwarp();

        int p = 0;
        unsigned long long head = smrg[warp][lane][0];
        for (int out = 0; out < KNB + 1; out++) {
            unsigned long long m = head;
#pragma unroll
            for (int off = 16; off; off >>= 1) {
                unsigned long long o = __shfl_xor_sync(0xffffffffu, m, off);
                if (o < m) m = o;
            }
            if (out > 0 && lane == 0)
                g_idx[q * KNB + out - 1] = (int)(unsigned)m;
            if (head == m) { p++; head = smrg[warp][lane][p]; }
        }
    }
}

__global__ __launch_bounds__(256, 2) void gemm_o_tc(float* __restrict__ C) {
    extern __shared__ __align__(128) char smem[];
    tc_gemm_body(smem, g_Ahi, g_Alo, g_Bh + (size_t)3 * DM * DM,
                 C, blockIdx.y * 128, blockIdx.x * 128);
}

// ---------------- attention: warp per (row, head), separable pe, hoisted loads ---
__global__ __launch_bounds__(256) void attn_kernel(const float* __restrict__ Wpos,
                                                   const float* __restrict__ bpos,
                                                   const float* __restrict__ temp) {
    int gw   = (blockIdx.x * blockDim.x + threadIdx.x) >> 5;
    int lane = threadIdx.x & 31;
    int row  = gw >> 3;
    int h    = gw & 7;
    int b    = row >> 12;
    int base = (b << 12);

    // lane k (<16) owns neighbor k and its relative position
    int j = 0;
    float rx = 0.f, ry = 0.f, rz = 0.f;
    float4 qp = g_pos4[row];
    if (lane < KNB) {
        j  = g_idx[row * KNB + lane];
        float4 p = g_pos4[base + j];
        rx = qp.x - p.x; ry = qp.y - p.y; rz = qp.z - p.z;
    }

    float invT = 1.0f / temp[0];
    float2 q = *(const float2*)&g_Q[(size_t)row * DM + h * DH + 2 * lane];
    q.x *= invT; q.y *= invT;
    float2 w0 = *(const float2*)&Wpos[0 * 128 + 2 * lane];
    float2 w1 = *(const float2*)&Wpos[1 * 128 + 2 * lane];
    float2 w2 = *(const float2*)&Wpos[2 * 128 + 2 * lane];
    float2 bp = *(const float2*)&bpos[2 * lane];

    // separable pe dot products: A=q.w0, B=q.w1, C=q.w2, D=q.bp (all-lane reduce)
    float pa = fmaf(q.x, w0.x, q.y * w0.y);
    float pb = fmaf(q.x, w1.x, q.y * w1.y);
    float pc = fmaf(q.x, w2.x, q.y * w2.y);
    float pd = fmaf(q.x, bp.x, q.y * bp.y);
#pragma unroll
    for (int off = 16; off; off >>= 1) {
        pa += __shfl_xor_sync(0xffffffffu, pa, off);
        pb += __shfl_xor_sync(0xffffffffu, pb, off);
        pc += __shfl_xor_sync(0xffffffffu, pc, off);
        pd += __shfl_xor_sync(0xffffffffu, pd, off);
    }

    // hoist all 16 K gathers (deep MLP)
    int jks[KNB];
#pragma unroll
    for (int k = 0; k < KNB; k++)
        jks[k] = __shfl_sync(0xffffffffu, j, k);
    float2 kvv[KNB];
#pragma unroll
    for (int k = 0; k < KNB; k++)
        kvv[k] = *(const float2*)&g_K[(size_t)(base + jks[k]) * DM + h * DH + 2 * lane];

    float myscore = 0.0f;
#pragma unroll
    for (int k = 0; k < KNB; k++) {
        float s = fmaf(q.x, kvv[k].x, q.y * kvv[k].y);
#pragma unroll
        for (int off = 16; off; off >>= 1)
            s += __shfl_xor_sync(0xffffffffu, s, off);
        if (lane == k) myscore = s;
    }
    // add separable pe contribution on owner lane
    myscore += fmaf(rx, pa, fmaf(ry, pb, fmaf(rz, pc, pd)));

    float sc = (lane < KNB) ? myscore : -INFINITY;
    float m = sc;
#pragma unroll
    for (int off = 8; off; off >>= 1)
        m = fmaxf(m, __shfl_xor_sync(0xffffffffu, m, off));
    float e = (lane < KNB) ? __expf(sc - m) : 0.0f;
    float sum = e;
#pragma unroll
    for (int off = 8; off; off >>= 1)
        sum += __shfl_xor_sync(0xffffffffu, sum, off);
    float w = e / sum;

    float2 acc = make_float2(0.f, 0.f);
#pragma unroll
    for (int k = 0; k < KNB; k++) {
        float wk = __shfl_sync(0xffffffffu, w, k);
        float2 v = *(const float2*)&g_V[(size_t)(base + jks[k]) * DM + h * DH + 2 * lane];
        acc.x = fmaf(wk, v.x, acc.x);
        acc.y = fmaf(wk, v.y, acc.y);
    }
    // write fp16 hi/lo split directly (feeds gemm_o)
    size_t off = (size_t)row * DM + h * DH + 2 * lane;
    __half h0 = __float2half(acc.x);
    __half h1 = __float2half(acc.y);
    __half l0 = __float2half(acc.x - __half2float(h0));
    __half l1 = __float2half(acc.y - __half2float(h1));
    *(uint32_t*)&g_Ahi[off] = pkh(h0, h1);
    *(uint32_t*)&g_Alo[off] = pkh(l0, l1);
}

// ---------------- epilogue: +bo, +residual, LayerNorm ----------------------------
__global__ __launch_bounds__(512) void ln_kernel(const float* __restrict__ feat,
                                                 const float* __restrict__ bo,
                                                 const float* __restrict__ gamma,
                                                 const float* __restrict__ beta,
                                                 float* __restrict__ out) {
    int row = blockIdx.x;
    int tid = threadIdx.x;
    int lane = tid & 31, warp = tid >> 5;
    __shared__ float red[16];
    __shared__ float mu_s, rs_s;

    float x = g_tmp[(size_t)row * DM + tid] + bo[tid] + feat[(size_t)row * DM + tid];

    float s = x;
#pragma unroll
    for (int o = 16; o; o >>= 1) s += __shfl_down_sync(0xffffffffu, s, o);
    if (!lane) red[warp] = s;
    __syncthreads();
    if (tid == 0) {
        float t = 0.0f;
#pragma unroll
        for (int i = 0; i < 16; i++) t += red[i];
        mu_s = t * (1.0f / DM);
    }
    __syncthreads();
    float mu = mu_s;
    float d = x - mu;
    float s2 = d * d;
#pragma unroll
    for (int o = 16; o; o >>= 1) s2 += __shfl_down_sync(0xffffffffu, s2, o);
    if (!lane) red[warp] = s2;
    __syncthreads();
    if (tid == 0) {
        float t = 0.0f;
#pragma unroll
        for (int i = 0; i < 16; i++) t += red[i];
        rs_s = rsqrtf(t * (1.0f / DM) + 1e-5f);
    }
    __syncthreads();
    out[(size_t)row * DM + tid] = d * rs_s * gamma[tid] + beta[tid];
}

// ---------------- launch ---------------------------------------------------------
extern "C" void kernel_launch(void* const* d_in, const int* in_sizes, int n_in,
                              void* d_out, int out_size) {
    const float* pos   = (const float*)d_in[0];
    const float* feat  = (const float*)d_in[1];
    const float* Wq    = (const float*)d_in[3];
    const float* Wk    = (const float*)d_in[4];
    const float* Wv    = (const float*)d_in[5];
    const float* Wo    = (const float*)d_in[6];
    const float* bo    = (const float*)d_in[7];
    const float* Wpos  = (const float*)d_in[8];
    const float* bpos  = (const float*)d_in[9];
    const float* temp  = (const float*)d_in[10];
    const float* gamma = (const float*)d_in[11];
    const float* beta  = (const float*)d_in[12];
    float* out = (float*)d_out;

    float *pQ, *pK, *pV, *pTmp;
    cudaGetSymbolAddress((void**)&pQ,   g_Q);
    cudaGetSymbolAddress((void**)&pK,   g_K);
    cudaGetSymbolAddress((void**)&pV,   g_V);
    cudaGetSymbolAddress((void**)&pTmp, g_tmp);

    cudaFuncSetAttribute(fused_qkv_knn, cudaFuncAttributeMaxDynamicSharedMemorySize, GEMM_SMEM);
    cudaFuncSetAttribute(gemm_o_tc,     cudaFuncAttributeMaxDynamicSharedMemorySize, GEMM_SMEM);

    prep_kernel<<<4096 + 1024 + 32, 256>>>(feat, pos, Wq, Wk, Wv, Wo);

    fused_qkv_knn<<<1792, 256, GEMM_SMEM>>>(pQ, pK, pV);

    attn_kernel<<<ROWS * NH * 32 / 256, 256>>>(Wpos, bpos, temp);

    gemm_o_tc<<<dim3(DM / 128, ROWS / 128), 256, GEMM_SMEM>>>(pTmp);

    ln_kernel<<<ROWS, 512>>>(feat, bo, gamma, beta, out);
}

// round 11
// speedup vs baseline: 1.2292x; 1.0882x over previous
#include <cuda_runtime.h>
#include <cuda_fp16.h>
#include <math.h>
#include <stdint.h>

#define BATCH 2
#define NPTS 4096
#define DM 512
#define NH 8
#define DH 64
#define KNB 16
#define ROWS (BATCH * NPTS)   // 8192

// ---------------- scratch (device globals; no allocation allowed) ----------------
__device__ float g_Q[ROWS * DM];
__device__ float g_K[ROWS * DM];
__device__ float g_V[ROWS * DM];
__device__ float g_tmp[ROWS * DM];
__device__ int   g_idx[ROWS * KNB];
__device__ float4 g_pos4[ROWS];               // padded positions (x,y,z,0)
__device__ __half g_Ah[ROWS * DM];            // activation fp16 (feat, later att)
__device__ __half g_Bh[4 * DM * DM];          // transposed weights, fp16

// ---------------- helpers --------------------------------------------------------
__device__ __forceinline__ uint32_t smem_u32(const void* p) {
    uint32_t a;
    asm("{ .reg .u64 t; cvta.to.shared.u64 t, %1; cvt.u32.u64 %0, t; }"
        : "=r"(a) : "l"(p));
    return a;
}
#define CP16(dst, src) \
    asm volatile("cp.async.cg.shared.global [%0], [%1], 16;" :: "r"(dst), "l"(src))
#define CP_COMMIT() asm volatile("cp.async.commit_group;" ::: "memory")
#define CP_WAIT(n)  asm volatile("cp.async.wait_group %0;" :: "n"(n) : "memory")

__device__ __forceinline__ void ldmx4(uint32_t* r, uint32_t addr) {
    asm volatile("ldmatrix.sync.aligned.m8n8.x4.shared.b16 {%0,%1,%2,%3}, [%4];"
                 : "=r"(r[0]), "=r"(r[1]), "=r"(r[2]), "=r"(r[3]) : "r"(addr));
}
__device__ __forceinline__ void mma16816(float* c, const uint32_t* a, const uint32_t* b) {
    asm volatile(
        "mma.sync.aligned.m16n8k16.row.col.f32.f16.f16.f32 "
        "{%0,%1,%2,%3}, {%4,%5,%6,%7}, {%8,%9}, {%0,%1,%2,%3};"
        : "+f"(c[0]), "+f"(c[1]), "+f"(c[2]), "+f"(c[3])
        : "r"(a[0]), "r"(a[1]), "r"(a[2]), "r"(a[3]), "r"(b[0]), "r"(b[1]));
}
__device__ __forceinline__ uint32_t pkh(__half a, __half b) {
    return ((uint32_t)__half_as_ushort(b) << 16) | __half_as_ushort(a);
}

// ---------------- prep: feat->fp16 + transpose weights->fp16 + pos4 --------------
__global__ __launch_bounds__(256) void prep_kernel(const float* __restrict__ feat,
                                                   const float* __restrict__ pos,
                                                   const float* __restrict__ W0,
                                                   const float* __restrict__ W1,
                                                   const float* __restrict__ W2,
                                                   const float* __restrict__ W3) {
    __shared__ float t[32][33];
    if (blockIdx.x < 4096) {                      // feat -> fp16
        int i = blockIdx.x * blockDim.x + threadIdx.x;
        float4 v = *(const float4*)&feat[(size_t)i * 4];
        uint2 h;
        h.x = pkh(__float2half(v.x), __float2half(v.y));
        h.y = pkh(__float2half(v.z), __float2half(v.w));
        *(uint2*)&g_Ah[(size_t)i * 4] = h;
    } else if (blockIdx.x < 4096 + 1024) {        // transpose weights -> fp16
        int id = blockIdx.x - 4096;               // 16 x 16 x 4
        int z = id >> 8;
        int by = ((id >> 4) & 15) * 32, bx = (id & 15) * 32;
        const float* src = (z == 0) ? W0 : (z == 1) ? W1 : (z == 2) ? W2 : W3;
        size_t zoff = (size_t)z * DM * DM;
        int tx = threadIdx.x & 31, ty = threadIdx.x >> 5;   // 32 x 8
#pragma unroll
        for (int i = 0; i < 32; i += 8)
            t[ty + i][tx] = src[(size_t)(by + ty + i) * DM + bx + tx];
        __syncthreads();
#pragma unroll
        for (int i = 0; i < 32; i += 8)
            g_Bh[zoff + (size_t)(bx + ty + i) * DM + by + tx] =
                __float2half(t[tx][ty + i]);
    } else {                                      // pos -> float4 (32 CTAs)
        int i = (blockIdx.x - 4096 - 1024) * blockDim.x + threadIdx.x;  // 0..8191
        g_pos4[i] = make_float4(pos[i * 3 + 0], pos[i * 3 + 1], pos[i * 3 + 2], 0.0f);
    }
}

// ---------------- HMMA fp16 1-term GEMM body -------------------------------------
// C = Ah * Bh^T.  Stage 32KB, BKC=64:
//   A region [0,16K):  128 rows x 128B (64 fp16); chunk = k-half index 0..7,
//     physical chunk = logical ^ (r & 7)  -> LDSM conflict-free.
//   B region [16K,32K): same for B rows (N dim).
#define BKC 64
#define NCH (DM / BKC)        // 8
#define ST_A 0
#define ST_B 16384
#define STAGE 32768
#define NSTG 3
#define GEMM_SMEM (NSTG * STAGE)   // 98304

__device__ __forceinline__ void stage_load(uint32_t sb, int slot, int koff, int tid,
                                           const __half* __restrict__ Ah,
                                           const __half* __restrict__ Bh,
                                           int bm, int bn) {
    uint32_t stg = sb + (uint32_t)slot * STAGE;
#pragma unroll
    for (int i = 0; i < 8; i++) {
        int v = i * 256 + tid;          // 0..2047
        int arr = v >> 10;              // 0:A 1:B
        int idx = v & 1023;
        int r = idx >> 3, c = idx & 7;
        const __half* g = arr ? Bh : Ah;
        int rowbase = arr ? bn : bm;
        uint32_t region = arr ? ST_B : ST_A;
        uint32_t dst = stg + region + (uint32_t)(r * 128 + ((c ^ (r & 7)) << 4));
        CP16(dst, &g[(size_t)(rowbase + r) * DM + koff + c * 8]);
    }
    CP_COMMIT();
}

__device__ __forceinline__ void tc_gemm_body(char* smem,
                                             const __half* __restrict__ Ah,
                                             const __half* __restrict__ Bh,
                                             float* __restrict__ C,
                                             int bm, int bn) {
    uint32_t sb = smem_u32(smem);
    int tid = threadIdx.x;             // 256
    int wid = tid >> 5, lane = tid & 31;
    int warp_m = wid & 3, warp_n = wid >> 2;       // 4 x 2 warps -> 32x64 warp tile

    float c[2][8][4];
#pragma unroll
    for (int mt = 0; mt < 2; mt++)
#pragma unroll
        for (int nt = 0; nt < 8; nt++)
#pragma unroll
            for (int e = 0; e < 4; e++) c[mt][nt][e] = 0.0f;

    int arow = warp_m * 32 + (lane & 15);
    int akh  = lane >> 4;
    int axor = arow & 7;
    int brow = warp_n * 64 + (lane & 7) + ((lane >> 4) << 3);
    int bkh  = (lane >> 3) & 1;
    int bxor = brow & 7;

    stage_load(sb, 0, 0,   tid, Ah, Bh, bm, bn);
    stage_load(sb, 1, BKC, tid, Ah, Bh, bm, bn);

    for (int kc = 0; kc < NCH; kc++) {
        if (kc == NCH - 1) { CP_WAIT(0); } else { CP_WAIT(1); }
        __syncthreads();
        if (kc + 2 < NCH)
            stage_load(sb, (kc + 2) % NSTG, (kc + 2) * BKC, tid, Ah, Bh, bm, bn);

        uint32_t stg = sb + (uint32_t)(kc % NSTG) * STAGE;
#pragma unroll
        for (int ks = 0; ks < 4; ks++) {
            uint32_t ah[2][4];
#pragma unroll
            for (int mt = 0; mt < 2; mt++) {
                uint32_t rbase = stg + ST_A + (uint32_t)((arow + mt * 16) * 128);
                ldmx4(ah[mt], rbase + (uint32_t)(((ks * 2 + akh) ^ axor) << 4));
            }
#pragma unroll
            for (int np = 0; np < 4; np++) {
                uint32_t rbase = stg + ST_B + (uint32_t)((brow + np * 16) * 128);
                uint32_t bh[4];
                ldmx4(bh, rbase + (uint32_t)(((ks * 2 + bkh) ^ bxor) << 4));
#pragma unroll
                for (int mt = 0; mt < 2; mt++) {
                    mma16816(c[mt][np * 2 + 0], ah[mt], &bh[0]);
                    mma16816(c[mt][np * 2 + 1], ah[mt], &bh[2]);
                }
            }
        }
        __syncthreads();
    }

    int gid = lane >> 2, t4 = lane & 3;
#pragma unroll
    for (int mt = 0; mt < 2; mt++) {
        int r = bm + warp_m * 32 + mt * 16 + gid;
#pragma unroll
        for (int nt = 0; nt < 8; nt++) {
            int col = bn + warp_n * 64 + nt * 8 + t4 * 2;
            *(float2*)&C[(size_t)r * DM + col] =
                make_float2(c[mt][nt][0], c[mt][nt][1]);
            *(float2*)&C[(size_t)(r + 8) * DM + col] =
                make_float2(c[mt][nt][2], c[mt][nt][3]);
        }
    }
}

// ---------------- fused: QKV GEMMs + kNN, interleaved CTA groups -----------------
#define QW 8
__global__ __launch_bounds__(256, 2) void fused_qkv_knn(float* __restrict__ Cq,
                                                        float* __restrict__ Ck,
                                                        float* __restrict__ Cv) {
    extern __shared__ __align__(128) char smem[];
    int g7 = blockIdx.x / 7, r7 = blockIdx.x % 7;

    if (r7 < 3) {
        int id = g7 * 3 + r7;              // 0..767
        int z  = id >> 8;
        int rem = id & 255;
        int bm = (rem >> 2) * 128, bn = (rem & 3) * 128;
        float* C = (z == 0) ? Cq : (z == 1) ? Ck : Cv;
        tc_gemm_body(smem, g_Ah, g_Bh + (size_t)z * DM * DM, C, bm, bn);
    } else {
        // ---- kNN CTA: warp per query, global-threshold pruned top-17 ----
        unsigned long long (*smrg)[32][KNB + 2] =
            (unsigned long long (*)[32][KNB + 2])smem;
        int warp = threadIdx.x >> 5, lane = threadIdx.x & 31;
        int q = (g7 * 4 + (r7 - 3)) * QW + warp;    // 0..8191
        int b = q >> 12;
        int base = b << 12;
        float4 qp = g_pos4[q];

        unsigned long long key[KNB + 1];
#pragma unroll
        for (int i = 0; i < KNB + 1; i++) key[i] = 0xFFFFFFFFFFFFFFFFull;
        unsigned long long Tb = 0xFFFFFFFFFFFFFFFFull;

        for (int step = 0; step < NPTS / 32; step++) {
            if ((step & 7) == 0) {
                unsigned long long w = key[KNB];
#pragma unroll
                for (int off = 16; off; off >>= 1) {
                    unsigned long long o = __shfl_xor_sync(0xffffffffu, w, off);
                    if (o < w) w = o;
                }
                Tb = w;
            }
            int j = step * 32 + lane;
            float4 p = g_pos4[base + j];
            float dx = qp.x - p.x;
            float dy = qp.y - p.y;
            float dz = qp.z - p.z;
            float d = fmaf(dx, dx, fmaf(dy, dy, dz * dz));
            unsigned long long kk =
                ((unsigned long long)__float_as_uint(d) << 32) | (unsigned)j;
            if (kk < Tb) {
#pragma unroll
                for (int p2 = KNB; p2 >= 1; p2--) {
                    unsigned long long lower = key[p2 - 1];
                    unsigned long long cur   = key[p2];
                    key[p2] = (kk >= cur) ? cur : ((kk >= lower) ? kk : lower);
                }
                key[0] = (kk < key[0]) ? kk : key[0];
            }
        }

#pragma unroll
        for (int i = 0; i < KNB + 1; i++) smrg[warp][lane][i] = key[i];
        smrg[warp][lane][KNB + 1] = 0xFFFFFFFFFFFFFFFFull;
        __syncwarp();

        int p = 0;
        unsigned long long head = smrg[warp][lane][0];
        for (int out = 0; out < KNB + 1; out++) {
            unsigned long long m = head;
#pragma unroll
            for (int off = 16; off; off >>= 1) {
                unsigned long long o = __shfl_xor_sync(0xffffffffu, m, off);
                if (o < m) m = o;
            }
            if (out > 0 && lane == 0)
                g_idx[q * KNB + out - 1] = (int)(unsigned)m;
            if (head == m) { p++; head = smrg[warp][lane][p]; }
        }
    }
}

__global__ __launch_bounds__(256, 2) void gemm_o_tc(float* __restrict__ C) {
    extern __shared__ __align__(128) char smem[];
    tc_gemm_body(smem, g_Ah, g_Bh + (size_t)3 * DM * DM,
                 C, blockIdx.y * 128, blockIdx.x * 128);
}

// ---------------- attention: warp per (row, head), separable pe, hoisted loads ---
__global__ __launch_bounds__(256) void attn_kernel(const float* __restrict__ Wpos,
                                                   const float* __restrict__ bpos,
                                                   const float* __restrict__ temp) {
    int gw   = (blockIdx.x * blockDim.x + threadIdx.x) >> 5;
    int lane = threadIdx.x & 31;
    int row  = gw >> 3;
    int h    = gw & 7;
    int b    = row >> 12;
    int base = (b << 12);

    int j = 0;
    float rx = 0.f, ry = 0.f, rz = 0.f;
    float4 qp = g_pos4[row];
    if (lane < KNB) {
        j  = g_idx[row * KNB + lane];
        float4 p = g_pos4[base + j];
        rx = qp.x - p.x; ry = qp.y - p.y; rz = qp.z - p.z;
    }

    float invT = 1.0f / temp[0];
    float2 q = *(const float2*)&g_Q[(size_t)row * DM + h * DH + 2 * lane];
    q.x *= invT; q.y *= invT;
    float2 w0 = *(const float2*)&Wpos[0 * 128 + 2 * lane];
    float2 w1 = *(const float2*)&Wpos[1 * 128 + 2 * lane];
    float2 w2 = *(const float2*)&Wpos[2 * 128 + 2 * lane];
    float2 bp = *(const float2*)&bpos[2 * lane];

    // separable pe dot products (all-lane reduce)
    float pa = fmaf(q.x, w0.x, q.y * w0.y);
    float pb = fmaf(q.x, w1.x, q.y * w1.y);
    float pc = fmaf(q.x, w2.x, q.y * w2.y);
    float pd = fmaf(q.x, bp.x, q.y * bp.y);
#pragma unroll
    for (int off = 16; off; off >>= 1) {
        pa += __shfl_xor_sync(0xffffffffu, pa, off);
        pb += __shfl_xor_sync(0xffffffffu, pb, off);
        pc += __shfl_xor_sync(0xffffffffu, pc, off);
        pd += __shfl_xor_sync(0xffffffffu, pd, off);
    }

    int jks[KNB];
#pragma unroll
    for (int k = 0; k < KNB; k++)
        jks[k] = __shfl_sync(0xffffffffu, j, k);
    float2 kvv[KNB];
#pragma unroll
    for (int k = 0; k < KNB; k++)
        kvv[k] = *(const float2*)&g_K[(size_t)(base + jks[k]) * DM + h * DH + 2 * lane];

    float myscore = 0.0f;
#pragma unroll
    for (int k = 0; k < KNB; k++) {
        float s = fmaf(q.x, kvv[k].x, q.y * kvv[k].y);
#pragma unroll
        for (int off = 16; off; off >>= 1)
            s += __shfl_xor_sync(0xffffffffu, s, off);
        if (lane == k) myscore = s;
    }
    myscore += fmaf(rx, pa, fmaf(ry, pb, fmaf(rz, pc, pd)));

    float sc = (lane < KNB) ? myscore : -INFINITY;
    float m = sc;
#pragma unroll
    for (int off = 8; off; off >>= 1)
        m = fmaxf(m, __shfl_xor_sync(0xffffffffu, m, off));
    float e = (lane < KNB) ? __expf(sc - m) : 0.0f;
    float sum = e;
#pragma unroll
    for (int off = 8; off; off >>= 1)
        sum += __shfl_xor_sync(0xffffffffu, sum, off);
    float w = e / sum;

    float2 acc = make_float2(0.f, 0.f);
#pragma unroll
    for (int k = 0; k < KNB; k++) {
        float wk = __shfl_sync(0xffffffffu, w, k);
        float2 v = *(const float2*)&g_V[(size_t)(base + jks[k]) * DM + h * DH + 2 * lane];
        acc.x = fmaf(wk, v.x, acc.x);
        acc.y = fmaf(wk, v.y, acc.y);
    }
    // write fp16 (feeds gemm_o)
    size_t off = (size_t)row * DM + h * DH + 2 * lane;
    *(uint32_t*)&g_Ah[off] = pkh(__float2half(acc.x), __float2half(acc.y));
}

// ---------------- epilogue: +bo, +residual, LayerNorm ----------------------------
__global__ __launch_bounds__(512) void ln_kernel(const float* __restrict__ feat,
                                                 const float* __restrict__ bo,
                                                 const float* __restrict__ gamma,
                                                 const float* __restrict__ beta,
                                                 float* __restrict__ out) {
    int row = blockIdx.x;
    int tid = threadIdx.x;
    int lane = tid & 31, warp = tid >> 5;
    __shared__ float red[16];
    __shared__ float mu_s, rs_s;

    float x = g_tmp[(size_t)row * DM + tid] + bo[tid] + feat[(size_t)row * DM + tid];

    float s = x;
#pragma unroll
    for (int o = 16; o; o >>= 1) s += __shfl_down_sync(0xffffffffu, s, o);
    if (!lane) red[warp] = s;
    __syncthreads();
    if (tid == 0) {
        float t = 0.0f;
#pragma unroll
        for (int i = 0; i < 16; i++) t += red[i];
        mu_s = t * (1.0f / DM);
    }
    __syncthreads();
    float mu = mu_s;
    float d = x - mu;
    float s2 = d * d;
#pragma unroll
    for (int o = 16; o; o >>= 1) s2 += __shfl_down_sync(0xffffffffu, s2, o);
    if (!lane) red[warp] = s2;
    __syncthreads();
    if (tid == 0) {
        float t = 0.0f;
#pragma unroll
        for (int i = 0; i < 16; i++) t += red[i];
        rs_s = rsqrtf(t * (1.0f / DM) + 1e-5f);
    }
    __syncthreads();
    out[(size_t)row * DM + tid] = d * rs_s * gamma[tid] + beta[tid];
}

// ---------------- launch ---------------------------------------------------------
extern "C" void kernel_launch(void* const* d_in, const int* in_sizes, int n_in,
                              void* d_out, int out_size) {
    const float* pos   = (const float*)d_in[0];
    const float* feat  = (const float*)d_in[1];
    const float* Wq    = (const float*)d_in[3];
    const float* Wk    = (const float*)d_in[4];
    const float* Wv    = (const float*)d_in[5];
    const float* Wo    = (const float*)d_in[6];
    const float* bo    = (const float*)d_in[7];
    const float* Wpos  = (const float*)d_in[8];
    const float* bpos  = (const float*)d_in[9];
    const float* temp  = (const float*)d_in[10];
    const float* gamma = (const float*)d_in[11];
    const float* beta  = (const float*)d_in[12];
    float* out = (float*)d_out;

    float *pQ, *pK, *pV, *pTmp;
    cudaGetSymbolAddress((void**)&pQ,   g_Q);
    cudaGetSymbolAddress((void**)&pK,   g_K);
    cudaGetSymbolAddress((void**)&pV,   g_V);
    cudaGetSymbolAddress((void**)&pTmp, g_tmp);

    cudaFuncSetAttribute(fused_qkv_knn, cudaFuncAttributeMaxDynamicSharedMemorySize, GEMM_SMEM);
    cudaFuncSetAttribute(gemm_o_tc,     cudaFuncAttributeMaxDynamicSharedMemorySize, GEMM_SMEM);

    prep_kernel<<<4096 + 1024 + 32, 256>>>(feat, pos, Wq, Wk, Wv, Wo);

    fused_qkv_knn<<<1792, 256, GEMM_SMEM>>>(pQ, pK, pV);

    attn_kernel<<<ROWS * NH * 32 / 256, 256>>>(Wpos, bpos, temp);

    gemm_o_tc<<<dim3(DM / 128, ROWS / 128), 256, GEMM_SMEM>>>(pTmp);

    ln_kernel<<<ROWS, 512>>>(feat, bo, gamma, beta, out);
}

// round 14
// speedup vs baseline: 1.2603x; 1.0252x over previous
#include <cuda_runtime.h>
#include <cuda_fp16.h>
#include <math.h>
#include <stdint.h>

#define BATCH 2
#define NPTS 4096
#define DM 512
#define NH 8
#define DH 64
#define KNB 16
#define ROWS (BATCH * NPTS)   // 8192

// ---------------- scratch (device globals; no allocation allowed) ----------------
__device__ __half g_Qh[ROWS * DM];
__device__ __half g_Kh[ROWS * DM];
__device__ __half g_Vh[ROWS * DM];
__device__ float  g_tmp[ROWS * DM];
__device__ int    g_idx[ROWS * KNB];
__device__ float4 g_pos4[ROWS];               // padded positions (x,y,z,0)
__device__ __half g_Ah[ROWS * DM];            // activation fp16 (feat, later att)
__device__ __half g_Bh[4 * DM * DM];          // transposed weights, fp16

// ---------------- helpers --------------------------------------------------------
__device__ __forceinline__ uint32_t smem_u32(const void* p) {
    uint32_t a;
    asm("{ .reg .u64 t; cvta.to.shared.u64 t, %1; cvt.u32.u64 %0, t; }"
        : "=r"(a) : "l"(p));
    return a;
}
#define CP16(dst, src) \
    asm volatile("cp.async.cg.shared.global [%0], [%1], 16;" :: "r"(dst), "l"(src))
#define CP_COMMIT() asm volatile("cp.async.commit_group;" ::: "memory")
#define CP_WAIT(n)  asm volatile("cp.async.wait_group %0;" :: "n"(n) : "memory")

__device__ __forceinline__ void ldmx4(uint32_t* r, uint32_t addr) {
    asm volatile("ldmatrix.sync.aligned.m8n8.x4.shared.b16 {%0,%1,%2,%3}, [%4];"
                 : "=r"(r[0]), "=r"(r[1]), "=r"(r[2]), "=r"(r[3]) : "r"(addr));
}
__device__ __forceinline__ void mma16816(float* c, const uint32_t* a, const uint32_t* b) {
    asm volatile(
        "mma.sync.aligned.m16n8k16.row.col.f32.f16.f16.f32 "
        "{%0,%1,%2,%3}, {%4,%5,%6,%7}, {%8,%9}, {%0,%1,%2,%3};"
        : "+f"(c[0]), "+f"(c[1]), "+f"(c[2]), "+f"(c[3])
        : "r"(a[0]), "r"(a[1]), "r"(a[2]), "r"(a[3]), "r"(b[0]), "r"(b[1]));
}
__device__ __forceinline__ uint32_t pkh(__half a, __half b) {
    return ((uint32_t)__half_as_ushort(b) << 16) | __half_as_ushort(a);
}

// ---------------- prep: feat->fp16 + transpose weights->fp16 + pos4 --------------
__global__ __launch_bounds__(256) void prep_kernel(const float* __restrict__ feat,
                                                   const float* __restrict__ pos,
                                                   const float* __restrict__ W0,
                                                   const float* __restrict__ W1,
                                                   const float* __restrict__ W2,
                                                   const float* __restrict__ W3) {
    __shared__ float t[32][33];
    if (blockIdx.x < 4096) {                      // feat -> fp16
        int i = blockIdx.x * blockDim.x + threadIdx.x;
        float4 v = *(const float4*)&feat[(size_t)i * 4];
        uint2 h;
        h.x = pkh(__float2half(v.x), __float2half(v.y));
        h.y = pkh(__float2half(v.z), __float2half(v.w));
        *(uint2*)&g_Ah[(size_t)i * 4] = h;
    } else if (blockIdx.x < 4096 + 1024) {        // transpose weights -> fp16
        int id = blockIdx.x - 4096;               // 16 x 16 x 4
        int z = id >> 8;
        int by = ((id >> 4) & 15) * 32, bx = (id & 15) * 32;
        const float* src = (z == 0) ? W0 : (z == 1) ? W1 : (z == 2) ? W2 : W3;
        size_t zoff = (size_t)z * DM * DM;
        int tx = threadIdx.x & 31, ty = threadIdx.x >> 5;   // 32 x 8
#pragma unroll
        for (int i = 0; i < 32; i += 8)
            t[ty + i][tx] = src[(size_t)(by + ty + i) * DM + bx + tx];
        __syncthreads();
#pragma unroll
        for (int i = 0; i < 32; i += 8)
            g_Bh[zoff + (size_t)(bx + ty + i) * DM + by + tx] =
                __float2half(t[tx][ty + i]);
    } else {                                      // pos -> float4 (32 CTAs)
        int i = (blockIdx.x - 4096 - 1024) * blockDim.x + threadIdx.x;  // 0..8191
        g_pos4[i] = make_float4(pos[i * 3 + 0], pos[i * 3 + 1], pos[i * 3 + 2], 0.0f);
    }
}

// ---------------- HMMA fp16 1-term GEMM body -------------------------------------
// C = Ah * Bh^T.  Stage 32KB, BKC=64; chunk xor (r&7) -> LDSM conflict-free.
#define BKC 64
#define NCH (DM / BKC)        // 8
#define ST_A 0
#define ST_B 16384
#define STAGE 32768
#define NSTG 3
#define GEMM_SMEM (NSTG * STAGE)   // 98304

__device__ __forceinline__ void stage_load(uint32_t sb, int slot, int koff, int tid,
                                           const __half* __restrict__ Ah,
                                           const __half* __restrict__ Bh,
                                           int bm, int bn) {
    uint32_t stg = sb + (uint32_t)slot * STAGE;
#pragma unroll
    for (int i = 0; i < 8; i++) {
        int v = i * 256 + tid;          // 0..2047
        int arr = v >> 10;              // 0:A 1:B
        int idx = v & 1023;
        int r = idx >> 3, c = idx & 7;
        const __half* g = arr ? Bh : Ah;
        int rowbase = arr ? bn : bm;
        uint32_t region = arr ? ST_B : ST_A;
        uint32_t dst = stg + region + (uint32_t)(r * 128 + ((c ^ (r & 7)) << 4));
        CP16(dst, &g[(size_t)(rowbase + r) * DM + koff + c * 8]);
    }
    CP_COMMIT();
}

template <bool HALF_OUT>
__device__ __forceinline__ void tc_gemm_body(char* smem,
                                             const __half* __restrict__ Ah,
                                             const __half* __restrict__ Bh,
                                             void* __restrict__ Cp,
                                             int bm, int bn) {
    uint32_t sb = smem_u32(smem);
    int tid = threadIdx.x;             // 256
    int wid = tid >> 5, lane = tid & 31;
    int warp_m = wid & 3, warp_n = wid >> 2;       // 4 x 2 warps -> 32x64 warp tile

    float c[2][8][4];
#pragma unroll
    for (int mt = 0; mt < 2; mt++)
#pragma unroll
        for (int nt = 0; nt < 8; nt++)
#pragma unroll
            for (int e = 0; e < 4; e++) c[mt][nt][e] = 0.0f;

    int arow = warp_m * 32 + (lane & 15);
    int akh  = lane >> 4;
    int axor = arow & 7;
    int brow = warp_n * 64 + (lane & 7) + ((lane >> 4) << 3);
    int bkh  = (lane >> 3) & 1;
    int bxor = brow & 7;

    stage_load(sb, 0, 0,   tid, Ah, Bh, bm, bn);
    stage_load(sb, 1, BKC, tid, Ah, Bh, bm, bn);

    for (int kc = 0; kc < NCH; kc++) {
        if (kc == NCH - 1) { CP_WAIT(0); } else { CP_WAIT(1); }
        __syncthreads();
        if (kc + 2 < NCH)
            stage_load(sb, (kc + 2) % NSTG, (kc + 2) * BKC, tid, Ah, Bh, bm, bn);

        uint32_t stg = sb + (uint32_t)(kc % NSTG) * STAGE;
#pragma unroll
        for (int ks = 0; ks < 4; ks++) {
            uint32_t ah[2][4];
#pragma unroll
            for (int mt = 0; mt < 2; mt++) {
                uint32_t rbase = stg + ST_A + (uint32_t)((arow + mt * 16) * 128);
                ldmx4(ah[mt], rbase + (uint32_t)(((ks * 2 + akh) ^ axor) << 4));
            }
#pragma unroll
            for (int np = 0; np < 4; np++) {
                uint32_t rbase = stg + ST_B + (uint32_t)((brow + np * 16) * 128);
                uint32_t bh[4];
                ldmx4(bh, rbase + (uint32_t)(((ks * 2 + bkh) ^ bxor) << 4));
#pragma unroll
                for (int mt = 0; mt < 2; mt++) {
                    mma16816(c[mt][np * 2 + 0], ah[mt], &bh[0]);
                    mma16816(c[mt][np * 2 + 1], ah[mt], &bh[2]);
                }
            }
        }
        __syncthreads();
    }

    int gid = lane >> 2, t4 = lane & 3;
#pragma unroll
    for (int mt = 0; mt < 2; mt++) {
        int r = bm + warp_m * 32 + mt * 16 + gid;
#pragma unroll
        for (int nt = 0; nt < 8; nt++) {
            int col = bn + warp_n * 64 + nt * 8 + t4 * 2;
            if (HALF_OUT) {
                __half* C = (__half*)Cp;
                *(uint32_t*)&C[(size_t)r * DM + col] =
                    pkh(__float2half(c[mt][nt][0]), __float2half(c[mt][nt][1]));
                *(uint32_t*)&C[(size_t)(r + 8) * DM + col] =
                    pkh(__float2half(c[mt][nt][2]), __float2half(c[mt][nt][3]));
            } else {
                float* C = (float*)Cp;
                *(float2*)&C[(size_t)r * DM + col] =
                    make_float2(c[mt][nt][0], c[mt][nt][1]);
                *(float2*)&C[(size_t)(r + 8) * DM + col] =
                    make_float2(c[mt][nt][2], c[mt][nt][3]);
            }
        }
    }
}

// ---------------- fused: QKV GEMMs (fp16 out) + kNN (smem positions) -------------
#define QW 8
__global__ __launch_bounds__(256, 2) void fused_qkv_knn(__half* __restrict__ Cq,
                                                        __half* __restrict__ Ck,
                                                        __half* __restrict__ Cv) {
    extern __shared__ __align__(128) char smem[];
    int g7 = blockIdx.x / 7, r7 = blockIdx.x % 7;

    if (r7 < 3) {
        int id = g7 * 3 + r7;              // 0..767
        int z  = id >> 8;
        int rem = id & 255;
        int bm = (rem >> 2) * 128, bn = (rem & 3) * 128;
        __half* C = (z == 0) ? Cq : (z == 1) ? Ck : Cv;
        tc_gemm_body<true>(smem, g_Ah, g_Bh + (size_t)z * DM * DM, C, bm, bn);
    } else {
        // ---- kNN CTA: smem-resident positions, warp per query -------------------
        float4* spos = (float4*)smem;                       // 4096 x 16B = 64KB
        int warp = threadIdx.x >> 5, lane = threadIdx.x & 31;
        int qbase = (g7 * 4 + (r7 - 3)) * QW;               // 8 queries, same batch
        int q = qbase + warp;
        int b = qbase >> 12;
        int base = b << 12;

        for (int i = threadIdx.x; i < NPTS; i += 256)
            spos[i] = g_pos4[base + i];
        __syncthreads();

        float4 qp = spos[q - base];

        unsigned long long key[KNB + 1];
#pragma unroll
        for (int i = 0; i < KNB + 1; i++) key[i] = 0xFFFFFFFFFFFFFFFFull;
        unsigned long long Tb = 0xFFFFFFFFFFFFFFFFull;

        for (int step = 0; step < NPTS / 32; step++) {
            if ((step & 7) == 0) {
                unsigned long long w = key[KNB];
#pragma unroll
                for (int off = 16; off; off >>= 1) {
                    unsigned long long o = __shfl_xor_sync(0xffffffffu, w, off);
                    if (o < w) w = o;
                }
                Tb = w;
            }
            int j = step * 32 + lane;
            float4 p = spos[j];
            float dx = qp.x - p.x;
            float dy = qp.y - p.y;
            float dz = qp.z - p.z;
            float d = fmaf(dx, dx, fmaf(dy, dy, dz * dz));
            unsigned long long kk =
                ((unsigned long long)__float_as_uint(d) << 32) | (unsigned)j;
            if (kk < Tb) {
#pragma unroll
                for (int p2 = KNB; p2 >= 1; p2--) {
                    unsigned long long lower = key[p2 - 1];
                    unsigned long long cur   = key[p2];
                    key[p2] = (kk >= cur) ? cur : ((kk >= lower) ? kk : lower);
                }
                key[0] = (kk < key[0]) ? kk : key[0];
            }
        }

        // positions no longer needed; alias merge buffer over smem
        __syncthreads();
        unsigned long long (*smrg)[32][KNB + 2] =
            (unsigned long long (*)[32][KNB + 2])smem;
#pragma unroll
        for (int i = 0; i < KNB + 1; i++) smrg[warp][lane][i] = key[i];
        smrg[warp][lane][KNB + 1] = 0xFFFFFFFFFFFFFFFFull;
        __syncwarp();

        int p = 0;
        unsigned long long head = smrg[warp][lane][0];
        for (int out = 0; out < KNB + 1; out++) {
            unsigned long long m = head;
#pragma unroll
            for (int off = 16; off; off >>= 1) {
                unsigned long long o = __shfl_xor_sync(0xffffffffu, m, off);
                if (o < m) m = o;
            }
            if (out > 0 && lane == 0)
                g_idx[q * KNB + out - 1] = (int)(unsigned)m;
            if (head == m) { p++; head = smrg[warp][lane][p]; }
        }
    }
}

__global__ __launch_bounds__(256, 2) void gemm_o_tc(float* __restrict__ C) {
    extern __shared__ __align__(128) char smem[];
    tc_gemm_body<false>(smem, g_Ah, g_Bh + (size_t)3 * DM * DM,
                        C, blockIdx.y * 128, blockIdx.x * 128);
}

// ---------------- attention: warp per (row, head), fp16 Q/K/V --------------------
__global__ __launch_bounds__(256) void attn_kernel(const float* __restrict__ Wpos,
                                                   const float* __restrict__ bpos,
                                                   const float* __restrict__ temp) {
    int gw   = (blockIdx.x * blockDim.x + threadIdx.x) >> 5;
    int lane = threadIdx.x & 31;
    int row  = gw >> 3;
    int h    = gw & 7;
    int b    = row >> 12;
    int base = (b << 12);

    int j = 0;
    float rx = 0.f, ry = 0.f, rz = 0.f;
    float4 qp = g_pos4[row];
    if (lane < KNB) {
        j  = g_idx[row * KNB + lane];
        float4 p = g_pos4[base + j];
        rx = qp.x - p.x; ry = qp.y - p.y; rz = qp.z - p.z;
    }

    float invT = 1.0f / temp[0];
    float2 q = __half22float2(*(const __half2*)&g_Qh[(size_t)row * DM + h * DH + 2 * lane]);
    q.x *= invT; q.y *= invT;
    float2 w0 = *(const float2*)&Wpos[0 * 128 + 2 * lane];
    float2 w1 = *(const float2*)&Wpos[1 * 128 + 2 * lane];
    float2 w2 = *(const float2*)&Wpos[2 * 128 + 2 * lane];
    float2 bp = *(const float2*)&bpos[2 * lane];

    // separable pe dot products (all-lane reduce)
    float pa = fmaf(q.x, w0.x, q.y * w0.y);
    float pb = fmaf(q.x, w1.x, q.y * w1.y);
    float pc = fmaf(q.x, w2.x, q.y * w2.y);
    float pd = fmaf(q.x, bp.x, q.y * bp.y);
#pragma unroll
    for (int off = 16; off; off >>= 1) {
        pa += __shfl_xor_sync(0xffffffffu, pa, off);
        pb += __shfl_xor_sync(0xffffffffu, pb, off);
        pc += __shfl_xor_sync(0xffffffffu, pc, off);
        pd += __shfl_xor_sync(0xffffffffu, pd, off);
    }

    int jks[KNB];
#pragma unroll
    for (int k = 0; k < KNB; k++)
        jks[k] = __shfl_sync(0xffffffffu, j, k);
    float2 kvv[KNB];
#pragma unroll
    for (int k = 0; k < KNB; k++)
        kvv[k] = __half22float2(
            *(const __half2*)&g_Kh[(size_t)(base + jks[k]) * DM + h * DH + 2 * lane]);

    float myscore = 0.0f;
#pragma unroll
    for (int k = 0; k < KNB; k++) {
        float s = fmaf(q.x, kvv[k].x, q.y * kvv[k].y);
#pragma unroll
        for (int off = 16; off; off >>= 1)
            s += __shfl_xor_sync(0xffffffffu, s, off);
        if (lane == k) myscore = s;
    }
    myscore += fmaf(rx, pa, fmaf(ry, pb, fmaf(rz, pc, pd)));

    float sc = (lane < KNB) ? myscore : -INFINITY;
    float m = sc;
#pragma unroll
    for (int off = 8; off; off >>= 1)
        m = fmaxf(m, __shfl_xor_sync(0xffffffffu, m, off));
    float e = (lane < KNB) ? __expf(sc - m) : 0.0f;
    float sum = e;
#pragma unroll
    for (int off = 8; off; off >>= 1)
        sum += __shfl_xor_sync(0xffffffffu, sum, off);
    float w = e / sum;

    float2 acc = make_float2(0.f, 0.f);
#pragma unroll
    for (int k = 0; k < KNB; k++) {
        float wk = __shfl_sync(0xffffffffu, w, k);
        float2 v = __half22float2(
            *(const __half2*)&g_Vh[(size_t)(base + jks[k]) * DM + h * DH + 2 * lane]);
        acc.x = fmaf(wk, v.x, acc.x);
        acc.y = fmaf(wk, v.y, acc.y);
    }
    size_t off = (size_t)row * DM + h * DH + 2 * lane;
    *(uint32_t*)&g_Ah[off] = pkh(__float2half(acc.x), __float2half(acc.y));
}

// ---------------- epilogue: +bo, +residual, LayerNorm ----------------------------
__global__ __launch_bounds__(512) void ln_kernel(const float* __restrict__ feat,
                                                 const float* __restrict__ bo,
                                                 const float* __restrict__ gamma,
                                                 const float* __restrict__ beta,
                                                 float* __restrict__ out) {
    int row = blockIdx.x;
    int tid = threadIdx.x;
    int lane = tid & 31, warp = tid >> 5;
    __shared__ float red[16];
    __shared__ float mu_s, rs_s;

    float x = g_tmp[(size_t)row * DM + tid] + bo[tid] + feat[(size_t)row * DM + tid];

    float s = x;
#pragma unroll
    for (int o = 16; o; o >>= 1) s += __shfl_down_sync(0xffffffffu, s, o);
    if (!lane) red[warp] = s;
    __syncthreads();
    if (tid == 0) {
        float t = 0.0f;
#pragma unroll
        for (int i = 0; i < 16; i++) t += red[i];
        mu_s = t * (1.0f / DM);
    }
    __syncthreads();
    float mu = mu_s;
    float d = x - mu;
    float s2 = d * d;
#pragma unroll
    for (int o = 16; o; o >>= 1) s2 += __shfl_down_sync(0xffffffffu, s2, o);
    if (!lane) red[warp] = s2;
    __syncthreads();
    if (tid == 0) {
        float t = 0.0f;
#pragma unroll
        for (int i = 0; i < 16; i++) t += red[i];
        rs_s = rsqrtf(t * (1.0f / DM) + 1e-5f);
    }
    __syncthreads();
    out[(size_t)row * DM + tid] = d * rs_s * gamma[tid] + beta[tid];
}

// ---------------- launch ---------------------------------------------------------
extern "C" void kernel_launch(void* const* d_in, const int* in_sizes, int n_in,
                              void* d_out, int out_size) {
    const float* pos   = (const float*)d_in[0];
    const float* feat  = (const float*)d_in[1];
    const float* Wq    = (const float*)d_in[3];
    const float* Wk    = (const float*)d_in[4];
    const float* Wv    = (const float*)d_in[5];
    const float* Wo    = (const float*)d_in[6];
    const float* bo    = (const float*)d_in[7];
    const float* Wpos  = (const float*)d_in[8];
    const float* bpos  = (const float*)d_in[9];
    const float* temp  = (const float*)d_in[10];
    const float* gamma = (const float*)d_in[11];
    const float* beta  = (const float*)d_in[12];
    float* out = (float*)d_out;

    __half *pQ, *pK, *pV;
    float *pTmp;
    cudaGetSymbolAddress((void**)&pQ,   g_Qh);
    cudaGetSymbolAddress((void**)&pK,   g_Kh);
    cudaGetSymbolAddress((void**)&pV,   g_Vh);
    cudaGetSymbolAddress((void**)&pTmp, g_tmp);

    cudaFuncSetAttribute(fused_qkv_knn, cudaFuncAttributeMaxDynamicSharedMemorySize, GEMM_SMEM);
    cudaFuncSetAttribute(gemm_o_tc,     cudaFuncAttributeMaxDynamicSharedMemorySize, GEMM_SMEM);

    prep_kernel<<<4096 + 1024 + 32, 256>>>(feat, pos, Wq, Wk, Wv, Wo);

    fused_qkv_knn<<<1792, 256, GEMM_SMEM>>>(pQ, pK, pV);

    attn_kernel<<<ROWS * NH * 32 / 256, 256>>>(Wpos, bpos, temp);

    gemm_o_tc<<<dim3(DM / 128, ROWS / 128), 256, GEMM_SMEM>>>(pTmp);

    ln_kernel<<<ROWS, 512>>>(feat, bo, gamma, beta, out);
}

// round 15
// speedup vs baseline: 1.3132x; 1.0420x over previous
#include <cuda_runtime.h>
#include <cuda_fp16.h>
#include <math.h>
#include <stdint.h>

#define BATCH 2
#define NPTS 4096
#define DM 512
#define NH 8
#define DH 64
#define KNB 16
#define ROWS (BATCH * NPTS)   // 8192

// ---------------- scratch (device globals; no allocation allowed) ----------------
__device__ __half g_Qh[ROWS * DM];
__device__ __half g_Kh[ROWS * DM];
__device__ __half g_Vh[ROWS * DM];
__device__ float  g_tmp[ROWS * DM];
__device__ int    g_idx[ROWS * KNB];
__device__ float4 g_pos4[ROWS];               // padded positions (x,y,z,0)
__device__ __half g_Ah[ROWS * DM];            // activation fp16 (feat, later att)
__device__ __half g_Bh[4 * DM * DM];          // transposed weights, fp16

// ---------------- helpers --------------------------------------------------------
__device__ __forceinline__ uint32_t smem_u32(const void* p) {
    uint32_t a;
    asm("{ .reg .u64 t; cvta.to.shared.u64 t, %1; cvt.u32.u64 %0, t; }"
        : "=r"(a) : "l"(p));
    return a;
}
#define CP16(dst, src) \
    asm volatile("cp.async.cg.shared.global [%0], [%1], 16;" :: "r"(dst), "l"(src))
#define CP_COMMIT() asm volatile("cp.async.commit_group;" ::: "memory")
#define CP_WAIT(n)  asm volatile("cp.async.wait_group %0;" :: "n"(n) : "memory")

__device__ __forceinline__ void ldmx4(uint32_t* r, uint32_t addr) {
    asm volatile("ldmatrix.sync.aligned.m8n8.x4.shared.b16 {%0,%1,%2,%3}, [%4];"
                 : "=r"(r[0]), "=r"(r[1]), "=r"(r[2]), "=r"(r[3]) : "r"(addr));
}
__device__ __forceinline__ void mma16816(float* c, const uint32_t* a, const uint32_t* b) {
    asm volatile(
        "mma.sync.aligned.m16n8k16.row.col.f32.f16.f16.f32 "
        "{%0,%1,%2,%3}, {%4,%5,%6,%7}, {%8,%9}, {%0,%1,%2,%3};"
        : "+f"(c[0]), "+f"(c[1]), "+f"(c[2]), "+f"(c[3])
        : "r"(a[0]), "r"(a[1]), "r"(a[2]), "r"(a[3]), "r"(b[0]), "r"(b[1]));
}
__device__ __forceinline__ uint32_t pkh(__half a, __half b) {
    return ((uint32_t)__half_as_ushort(b) << 16) | __half_as_ushort(a);
}

// ---------------- prep: feat->fp16 + transpose weights->fp16 + pos4 --------------
__global__ __launch_bounds__(256) void prep_kernel(const float* __restrict__ feat,
                                                   const float* __restrict__ pos,
                                                   const float* __restrict__ W0,
                                                   const float* __restrict__ W1,
                                                   const float* __restrict__ W2,
                                                   const float* __restrict__ W3) {
    __shared__ float t[32][33];
    if (blockIdx.x < 4096) {                      // feat -> fp16
        int i = blockIdx.x * blockDim.x + threadIdx.x;
        float4 v = *(const float4*)&feat[(size_t)i * 4];
        uint2 h;
        h.x = pkh(__float2half(v.x), __float2half(v.y));
        h.y = pkh(__float2half(v.z), __float2half(v.w));
        *(uint2*)&g_Ah[(size_t)i * 4] = h;
    } else if (blockIdx.x < 4096 + 1024) {        // transpose weights -> fp16
        int id = blockIdx.x - 4096;               // 16 x 16 x 4
        int z = id >> 8;
        int by = ((id >> 4) & 15) * 32, bx = (id & 15) * 32;
        const float* src = (z == 0) ? W0 : (z == 1) ? W1 : (z == 2) ? W2 : W3;
        size_t zoff = (size_t)z * DM * DM;
        int tx = threadIdx.x & 31, ty = threadIdx.x >> 5;   // 32 x 8
#pragma unroll
        for (int i = 0; i < 32; i += 8)
            t[ty + i][tx] = src[(size_t)(by + ty + i) * DM + bx + tx];
        __syncthreads();
#pragma unroll
        for (int i = 0; i < 32; i += 8)
            g_Bh[zoff + (size_t)(bx + ty + i) * DM + by + tx] =
                __float2half(t[tx][ty + i]);
    } else {                                      // pos -> float4 (32 CTAs)
        int i = (blockIdx.x - 4096 - 1024) * blockDim.x + threadIdx.x;  // 0..8191
        g_pos4[i] = make_float4(pos[i * 3 + 0], pos[i * 3 + 1], pos[i * 3 + 2], 0.0f);
    }
}

// ---------------- HMMA fp16 1-term GEMM body -------------------------------------
// C = Ah * Bh^T.  Stage 32KB, BKC=64; chunk xor (r&7) -> LDSM conflict-free.
// Inner loop preloads B-fragments in pairs so LDSM latency hides under MMAs.
#define BKC 64
#define NCH (DM / BKC)        // 8
#define ST_A 0
#define ST_B 16384
#define STAGE 32768
#define NSTG 3
#define GEMM_SMEM (NSTG * STAGE)   // 98304

__device__ __forceinline__ void stage_load(uint32_t sb, int slot, int koff, int tid,
                                           const __half* __restrict__ Ah,
                                           const __half* __restrict__ Bh,
                                           int bm, int bn) {
    uint32_t stg = sb + (uint32_t)slot * STAGE;
#pragma unroll
    for (int i = 0; i < 8; i++) {
        int v = i * 256 + tid;          // 0..2047
        int arr = v >> 10;              // 0:A 1:B
        int idx = v & 1023;
        int r = idx >> 3, c = idx & 7;
        const __half* g = arr ? Bh : Ah;
        int rowbase = arr ? bn : bm;
        uint32_t region = arr ? ST_B : ST_A;
        uint32_t dst = stg + region + (uint32_t)(r * 128 + ((c ^ (r & 7)) << 4));
        CP16(dst, &g[(size_t)(rowbase + r) * DM + koff + c * 8]);
    }
    CP_COMMIT();
}

template <bool HALF_OUT>
__device__ __forceinline__ void tc_gemm_body(char* smem,
                                             const __half* __restrict__ Ah,
                                             const __half* __restrict__ Bh,
                                             void* __restrict__ Cp,
                                             int bm, int bn) {
    uint32_t sb = smem_u32(smem);
    int tid = threadIdx.x;             // 256
    int wid = tid >> 5, lane = tid & 31;
    int warp_m = wid & 3, warp_n = wid >> 2;       // 4 x 2 warps -> 32x64 warp tile

    float c[2][8][4];
#pragma unroll
    for (int mt = 0; mt < 2; mt++)
#pragma unroll
        for (int nt = 0; nt < 8; nt++)
#pragma unroll
            for (int e = 0; e < 4; e++) c[mt][nt][e] = 0.0f;

    int arow = warp_m * 32 + (lane & 15);
    int akh  = lane >> 4;
    int axor = arow & 7;
    int brow = warp_n * 64 + (lane & 7) + ((lane >> 4) << 3);
    int bkh  = (lane >> 3) & 1;
    int bxor = brow & 7;

    stage_load(sb, 0, 0,   tid, Ah, Bh, bm, bn);
    stage_load(sb, 1, BKC, tid, Ah, Bh, bm, bn);

    for (int kc = 0; kc < NCH; kc++) {
        if (kc == NCH - 1) { CP_WAIT(0); } else { CP_WAIT(1); }
        __syncthreads();
        if (kc + 2 < NCH)
            stage_load(sb, (kc + 2) % NSTG, (kc + 2) * BKC, tid, Ah, Bh, bm, bn);

        uint32_t stg = sb + (uint32_t)(kc % NSTG) * STAGE;
#pragma unroll
        for (int ks = 0; ks < 4; ks++) {
            uint32_t ach = (uint32_t)(((ks * 2 + akh) ^ axor) << 4);
            uint32_t bch = (uint32_t)(((ks * 2 + bkh) ^ bxor) << 4);
            uint32_t ah[2][4];
#pragma unroll
            for (int mt = 0; mt < 2; mt++)
                ldmx4(ah[mt], stg + ST_A + (uint32_t)((arow + mt * 16) * 128) + ach);
            // B-fragments preloaded two np at a time: LDSM latency overlaps MMAs
#pragma unroll
            for (int npp = 0; npp < 2; npp++) {
                uint32_t bh0[4], bh1[4];
                ldmx4(bh0, stg + ST_B + (uint32_t)((brow + (npp * 2 + 0) * 16) * 128) + bch);
                ldmx4(bh1, stg + ST_B + (uint32_t)((brow + (npp * 2 + 1) * 16) * 128) + bch);
#pragma unroll
                for (int mt = 0; mt < 2; mt++) {
                    mma16816(c[mt][(npp * 2 + 0) * 2 + 0], ah[mt], &bh0[0]);
                    mma16816(c[mt][(npp * 2 + 0) * 2 + 1], ah[mt], &bh0[2]);
                    mma16816(c[mt][(npp * 2 + 1) * 2 + 0], ah[mt], &bh1[0]);
                    mma16816(c[mt][(npp * 2 + 1) * 2 + 1], ah[mt], &bh1[2]);
                }
            }
        }
        __syncthreads();
    }

    int gid = lane >> 2, t4 = lane & 3;
#pragma unroll
    for (int mt = 0; mt < 2; mt++) {
        int r = bm + warp_m * 32 + mt * 16 + gid;
#pragma unroll
        for (int nt = 0; nt < 8; nt++) {
            int col = bn + warp_n * 64 + nt * 8 + t4 * 2;
            if (HALF_OUT) {
                __half* C = (__half*)Cp;
                *(uint32_t*)&C[(size_t)r * DM + col] =
                    pkh(__float2half(c[mt][nt][0]), __float2half(c[mt][nt][1]));
                *(uint32_t*)&C[(size_t)(r + 8) * DM + col] =
                    pkh(__float2half(c[mt][nt][2]), __float2half(c[mt][nt][3]));
            } else {
                float* C = (float*)Cp;
                *(float2*)&C[(size_t)r * DM + col] =
                    make_float2(c[mt][nt][0], c[mt][nt][1]);
                *(float2*)&C[(size_t)(r + 8) * DM + col] =
                    make_float2(c[mt][nt][2], c[mt][nt][3]);
            }
        }
    }
}

// ---------------- fused: QKV GEMMs (fp16 out) + kNN (smem positions) -------------
#define QW 8
__global__ __launch_bounds__(256, 2) void fused_qkv_knn(__half* __restrict__ Cq,
                                                        __half* __restrict__ Ck,
                                                        __half* __restrict__ Cv) {
    extern __shared__ __align__(128) char smem[];
    int g7 = blockIdx.x / 7, r7 = blockIdx.x % 7;

    if (r7 < 3) {
        int id = g7 * 3 + r7;              // 0..767
        int z  = id >> 8;
        int rem = id & 255;
        int bm = (rem >> 2) * 128, bn = (rem & 3) * 128;
        __half* C = (z == 0) ? Cq : (z == 1) ? Ck : Cv;
        tc_gemm_body<true>(smem, g_Ah, g_Bh + (size_t)z * DM * DM, C, bm, bn);
    } else {
        // ---- kNN CTA: smem-resident positions, warp per query -------------------
        float4* spos = (float4*)smem;                       // 4096 x 16B = 64KB
        int warp = threadIdx.x >> 5, lane = threadIdx.x & 31;
        int qbase = (g7 * 4 + (r7 - 3)) * QW;               // 8 queries, same batch
        int q = qbase + warp;
        int b = qbase >> 12;
        int base = b << 12;

        for (int i = threadIdx.x; i < NPTS; i += 256)
            spos[i] = g_pos4[base + i];
        __syncthreads();

        float4 qp = spos[q - base];

        unsigned long long key[KNB + 1];
#pragma unroll
        for (int i = 0; i < KNB + 1; i++) key[i] = 0xFFFFFFFFFFFFFFFFull;
        unsigned long long Tb = 0xFFFFFFFFFFFFFFFFull;

        for (int step = 0; step < NPTS / 32; step++) {
            if ((step & 7) == 0) {
                unsigned long long w = key[KNB];
#pragma unroll
                for (int off = 16; off; off >>= 1) {
                    unsigned long long o = __shfl_xor_sync(0xffffffffu, w, off);
                    if (o < w) w = o;
                }
                Tb = w;
            }
            int j = step * 32 + lane;
            float4 p = spos[j];
            float dx = qp.x - p.x;
            float dy = qp.y - p.y;
            float dz = qp.z - p.z;
            float d = fmaf(dx, dx, fmaf(dy, dy, dz * dz));
            unsigned long long kk =
                ((unsigned long long)__float_as_uint(d) << 32) | (unsigned)j;
            if (kk < Tb) {
#pragma unroll
                for (int p2 = KNB; p2 >= 1; p2--) {
                    unsigned long long lower = key[p2 - 1];
                    unsigned long long cur   = key[p2];
                    key[p2] = (kk >= cur) ? cur : ((kk >= lower) ? kk : lower);
                }
                key[0] = (kk < key[0]) ? kk : key[0];
            }
        }

        // positions no longer needed; alias merge buffer over smem
        __syncthreads();
        unsigned long long (*smrg)[32][KNB + 2] =
            (unsigned long long (*)[32][KNB + 2])smem;
#pragma unroll
        for (int i = 0; i < KNB + 1; i++) smrg[warp][lane][i] = key[i];
        smrg[warp][lane][KNB + 1] = 0xFFFFFFFFFFFFFFFFull;
        __syncwarp();

        int p = 0;
        unsigned long long head = smrg[warp][lane][0];
        for (int out = 0; out < KNB + 1; out++) {
            unsigned long long m = head;
#pragma unroll
            for (int off = 16; off; off >>= 1) {
                unsigned long long o = __shfl_xor_sync(0xffffffffu, m, off);
                if (o < m) m = o;
            }
            if (out > 0 && lane == 0)
                g_idx[q * KNB + out - 1] = (int)(unsigned)m;
            if (head == m) { p++; head = smrg[warp][lane][p]; }
        }
    }
}

__global__ __launch_bounds__(256, 2) void gemm_o_tc(float* __restrict__ C) {
    extern __shared__ __align__(128) char smem[];
    tc_gemm_body<false>(smem, g_Ah, g_Bh + (size_t)3 * DM * DM,
                        C, blockIdx.y * 128, blockIdx.x * 128);
}

// ---------------- attention: warp per (row, head), fp16 Q/K/V --------------------
__global__ __launch_bounds__(256) void attn_kernel(const float* __restrict__ Wpos,
                                                   const float* __restrict__ bpos,
                                                   const float* __restrict__ temp) {
    int gw   = (blockIdx.x * blockDim.x + threadIdx.x) >> 5;
    int lane = threadIdx.x & 31;
    int row  = gw >> 3;
    int h    = gw & 7;
    int b    = row >> 12;
    int base = (b << 12);

    int j = 0;
    float rx = 0.f, ry = 0.f, rz = 0.f;
    float4 qp = g_pos4[row];
    if (lane < KNB) {
        j  = g_idx[row * KNB + lane];
        float4 p = g_pos4[base + j];
        rx = qp.x - p.x; ry = qp.y - p.y; rz = qp.z - p.z;
    }

    float invT = 1.0f / temp[0];
    float2 q = __half22float2(*(const __half2*)&g_Qh[(size_t)row * DM + h * DH + 2 * lane]);
    q.x *= invT; q.y *= invT;
    float2 w0 = *(const float2*)&Wpos[0 * 128 + 2 * lane];
    float2 w1 = *(const float2*)&Wpos[1 * 128 + 2 * lane];
    float2 w2 = *(const float2*)&Wpos[2 * 128 + 2 * lane];
    float2 bp = *(const float2*)&bpos[2 * lane];

    // separable pe dot products (all-lane reduce)
    float pa = fmaf(q.x, w0.x, q.y * w0.y);
    float pb = fmaf(q.x, w1.x, q.y * w1.y);
    float pc = fmaf(q.x, w2.x, q.y * w2.y);
    float pd = fmaf(q.x, bp.x, q.y * bp.y);
#pragma unroll
    for (int off = 16; off; off >>= 1) {
        pa += __shfl_xor_sync(0xffffffffu, pa, off);
        pb += __shfl_xor_sync(0xffffffffu, pb, off);
        pc += __shfl_xor_sync(0xffffffffu, pc, off);
        pd += __shfl_xor_sync(0xffffffffu, pd, off);
    }

    int jks[KNB];
#pragma unroll
    for (int k = 0; k < KNB; k++)
        jks[k] = __shfl_sync(0xffffffffu, j, k);
    float2 kvv[KNB];
#pragma unroll
    for (int k = 0; k < KNB; k++)
        kvv[k] = __half22float2(
            *(const __half2*)&g_Kh[(size_t)(base + jks[k]) * DM + h * DH + 2 * lane]);

    float myscore = 0.0f;
#pragma unroll
    for (int k = 0; k < KNB; k++) {
        float s = fmaf(q.x, kvv[k].x, q.y * kvv[k].y);
#pragma unroll
        for (int off = 16; off; off >>= 1)
            s += __shfl_xor_sync(0xffffffffu, s, off);
        if (lane == k) myscore = s;
    }
    myscore += fmaf(rx, pa, fmaf(ry, pb, fmaf(rz, pc, pd)));

    float sc = (lane < KNB) ? myscore : -INFINITY;
    float m = sc;
#pragma unroll
    for (int off = 8; off; off >>= 1)
        m = fmaxf(m, __shfl_xor_sync(0xffffffffu, m, off));
    float e = (lane < KNB) ? __expf(sc - m) : 0.0f;
    float sum = e;
#pragma unroll
    for (int off = 8; off; off >>= 1)
        sum += __shfl_xor_sync(0xffffffffu, sum, off);
    float w = e / sum;

    float2 acc = make_float2(0.f, 0.f);
#pragma unroll
    for (int k = 0; k < KNB; k++) {
        float wk = __shfl_sync(0xffffffffu, w, k);
        float2 v = __half22float2(
            *(const __half2*)&g_Vh[(size_t)(base + jks[k]) * DM + h * DH + 2 * lane]);
        acc.x = fmaf(wk, v.x, acc.x);
        acc.y = fmaf(wk, v.y, acc.y);
    }
    size_t off = (size_t)row * DM + h * DH + 2 * lane;
    *(uint32_t*)&g_Ah[off] = pkh(__float2half(acc.x), __float2half(acc.y));
}

// ---------------- epilogue: warp-per-row +bo, +residual, LayerNorm ---------------
__global__ __launch_bounds__(256) void ln_kernel(const float* __restrict__ feat,
                                                 const float* __restrict__ bo,
                                                 const float* __restrict__ gamma,
                                                 const float* __restrict__ beta,
                                                 float* __restrict__ out) {
    int warp = threadIdx.x >> 5, lane = threadIdx.x & 31;
    int row  = blockIdx.x * 8 + warp;          // 1024 CTAs x 8 warps

    // lane owns cols lane*4 + i*128, i=0..3 (coalesced float4 across the warp)
    float4 x[4];
    float s = 0.0f;
#pragma unroll
    for (int i = 0; i < 4; i++) {
        int col = lane * 4 + i * 128;
        float4 a = *(const float4*)&g_tmp[(size_t)row * DM + col];
        float4 f = *(const float4*)&feat[(size_t)row * DM + col];
        float4 bb = *(const float4*)&bo[col];
        x[i] = make_float4(a.x + f.x + bb.x, a.y + f.y + bb.y,
                           a.z + f.z + bb.z, a.w + f.w + bb.w);
        s += x[i].x + x[i].y + x[i].z + x[i].w;
    }
#pragma unroll
    for (int o = 16; o; o >>= 1) s += __shfl_xor_sync(0xffffffffu, s, o);
    float mu = s * (1.0f / DM);

    float v = 0.0f;
#pragma unroll
    for (int i = 0; i < 4; i++) {
        float dx = x[i].x - mu, dy = x[i].y - mu, dz = x[i].z - mu, dw = x[i].w - mu;
        v += dx * dx + dy * dy + dz * dz + dw * dw;
    }
#pragma unroll
    for (int o = 16; o; o >>= 1) v += __shfl_xor_sync(0xffffffffu, v, o);
    float rs = rsqrtf(v * (1.0f / DM) + 1e-5f);

#pragma unroll
    for (int i = 0; i < 4; i++) {
        int col = lane * 4 + i * 128;
        float4 g = *(const float4*)&gamma[col];
        float4 be = *(const float4*)&beta[col];
        float4 o4;
        o4.x = (x[i].x - mu) * rs * g.x + be.x;
        o4.y = (x[i].y - mu) * rs * g.y + be.y;
        o4.z = (x[i].z - mu) * rs * g.z + be.z;
        o4.w = (x[i].w - mu) * rs * g.w + be.w;
        *(float4*)&out[(size_t)row * DM + col] = o4;
    }
}

// ---------------- launch ---------------------------------------------------------
extern "C" void kernel_launch(void* const* d_in, const int* in_sizes, int n_in,
                              void* d_out, int out_size) {
    const float* pos   = (const float*)d_in[0];
    const float* feat  = (const float*)d_in[1];
    const float* Wq    = (const float*)d_in[3];
    const float* Wk    = (const float*)d_in[4];
    const float* Wv    = (const float*)d_in[5];
    const float* Wo    = (const float*)d_in[6];
    const float* bo    = (const float*)d_in[7];
    const float* Wpos  = (const float*)d_in[8];
    const float* bpos  = (const float*)d_in[9];
    const float* temp  = (const float*)d_in[10];
    const float* gamma = (const float*)d_in[11];
    const float* beta  = (const float*)d_in[12];
    float* out = (float*)d_out;

    __half *pQ, *pK, *pV;
    float *pTmp;
    cudaGetSymbolAddress((void**)&pQ,   g_Qh);
    cudaGetSymbolAddress((void**)&pK,   g_Kh);
    cudaGetSymbolAddress((void**)&pV,   g_Vh);
    cudaGetSymbolAddress((void**)&pTmp, g_tmp);

    cudaFuncSetAttribute(fused_qkv_knn, cudaFuncAttributeMaxDynamicSharedMemorySize, GEMM_SMEM);
    cudaFuncSetAttribute(gemm_o_tc,     cudaFuncAttributeMaxDynamicSharedMemorySize, GEMM_SMEM);

    prep_kernel<<<4096 + 1024 + 32, 256>>>(feat, pos, Wq, Wk, Wv, Wo);

    fused_qkv_knn<<<1792, 256, GEMM_SMEM>>>(pQ, pK, pV);

    attn_kernel<<<ROWS * NH * 32 / 256, 256>>>(Wpos, bpos, temp);

    gemm_o_tc<<<dim3(DM / 128, ROWS / 128), 256, GEMM_SMEM>>>(pTmp);

    ln_kernel<<<ROWS / 8, 256>>>(feat, bo, gamma, beta, out);
}

// round 16
// speedup vs baseline: 1.3292x; 1.0123x over previous
#include <cuda_runtime.h>
#include <cuda_fp16.h>
#include <math.h>
#include <stdint.h>

#define BATCH 2
#define NPTS 4096
#define DM 512
#define NH 8
#define DH 64
#define KNB 16
#define ROWS (BATCH * NPTS)   // 8192

// ---------------- scratch (device globals; no allocation allowed) ----------------
__device__ __half g_Qh[ROWS * DM];
__device__ __half g_Kh[ROWS * DM];
__device__ __half g_Vh[ROWS * DM];
__device__ float  g_tmp[ROWS * DM];
__device__ int    g_idx[ROWS * KNB];
__device__ float4 g_pos4[ROWS];               // padded positions (x,y,z,0)
__device__ __half g_Ah[ROWS * DM];            // activation fp16 (feat, later att)
__device__ __half g_Bh[4 * DM * DM];          // transposed weights, fp16

// ---------------- helpers --------------------------------------------------------
__device__ __forceinline__ uint32_t smem_u32(const void* p) {
    uint32_t a;
    asm("{ .reg .u64 t; cvta.to.shared.u64 t, %1; cvt.u32.u64 %0, t; }"
        : "=r"(a) : "l"(p));
    return a;
}
#define CP16(dst, src) \
    asm volatile("cp.async.cg.shared.global [%0], [%1], 16;" :: "r"(dst), "l"(src))
#define CP_COMMIT() asm volatile("cp.async.commit_group;" ::: "memory")
#define CP_WAIT(n)  asm volatile("cp.async.wait_group %0;" :: "n"(n) : "memory")

__device__ __forceinline__ void ldmx4(uint32_t* r, uint32_t addr) {
    asm volatile("ldmatrix.sync.aligned.m8n8.x4.shared.b16 {%0,%1,%2,%3}, [%4];"
                 : "=r"(r[0]), "=r"(r[1]), "=r"(r[2]), "=r"(r[3]) : "r"(addr));
}
__device__ __forceinline__ void mma16816(float* c, const uint32_t* a, const uint32_t* b) {
    asm volatile(
        "mma.sync.aligned.m16n8k16.row.col.f32.f16.f16.f32 "
        "{%0,%1,%2,%3}, {%4,%5,%6,%7}, {%8,%9}, {%0,%1,%2,%3};"
        : "+f"(c[0]), "+f"(c[1]), "+f"(c[2]), "+f"(c[3])
        : "r"(a[0]), "r"(a[1]), "r"(a[2]), "r"(a[3]), "r"(b[0]), "r"(b[1]));
}
__device__ __forceinline__ uint32_t pkh(__half a, __half b) {
    return ((uint32_t)__half_as_ushort(b) << 16) | __half_as_ushort(a);
}

// ---------------- prep: feat->fp16 (MLP=8) + transpose weights + pos4 ------------
__global__ __launch_bounds__(256) void prep_kernel(const float* __restrict__ feat,
                                                   const float* __restrict__ pos,
                                                   const float* __restrict__ W0,
                                                   const float* __restrict__ W1,
                                                   const float* __restrict__ W2,
                                                   const float* __restrict__ W3) {
    __shared__ float t[32][33];
    if (blockIdx.x < 512) {                       // feat -> fp16, 8 float4/thread
        size_t base = (size_t)blockIdx.x * 2048 + threadIdx.x;
        float4 v[8];
#pragma unroll
        for (int i = 0; i < 8; i++)
            v[i] = *(const float4*)&feat[(base + i * 256) * 4];
#pragma unroll
        for (int i = 0; i < 8; i++) {
            uint2 h;
            h.x = pkh(__float2half(v[i].x), __float2half(v[i].y));
            h.y = pkh(__float2half(v[i].z), __float2half(v[i].w));
            *(uint2*)&g_Ah[(base + i * 256) * 4] = h;
        }
    } else if (blockIdx.x < 512 + 1024) {         // transpose weights -> fp16
        int id = blockIdx.x - 512;                // 16 x 16 x 4
        int z = id >> 8;
        int by = ((id >> 4) & 15) * 32, bx = (id & 15) * 32;
        const float* src = (z == 0) ? W0 : (z == 1) ? W1 : (z == 2) ? W2 : W3;
        size_t zoff = (size_t)z * DM * DM;
        int tx = threadIdx.x & 31, ty = threadIdx.x >> 5;   // 32 x 8
#pragma unroll
        for (int i = 0; i < 32; i += 8)
            t[ty + i][tx] = src[(size_t)(by + ty + i) * DM + bx + tx];
        __syncthreads();
#pragma unroll
        for (int i = 0; i < 32; i += 8)
            g_Bh[zoff + (size_t)(bx + ty + i) * DM + by + tx] =
                __float2half(t[tx][ty + i]);
    } else {                                      // pos -> float4 (32 CTAs)
        int i = (blockIdx.x - 512 - 1024) * blockDim.x + threadIdx.x;  // 0..8191
        g_pos4[i] = make_float4(pos[i * 3 + 0], pos[i * 3 + 1], pos[i * 3 + 2], 0.0f);
    }
}

// ---------------- HMMA fp16 1-term GEMM body -------------------------------------
#define BKC 64
#define NCH (DM / BKC)        // 8
#define ST_A 0
#define ST_B 16384
#define STAGE 32768
#define NSTG 3
#define GEMM_SMEM (NSTG * STAGE)   // 98304

__device__ __forceinline__ void stage_load(uint32_t sb, int slot, int koff, int tid,
                                           const __half* __restrict__ Ah,
                                           const __half* __restrict__ Bh,
                                           int bm, int bn) {
    uint32_t stg = sb + (uint32_t)slot * STAGE;
#pragma unroll
    for (int i = 0; i < 8; i++) {
        int v = i * 256 + tid;          // 0..2047
        int arr = v >> 10;              // 0:A 1:B
        int idx = v & 1023;
        int r = idx >> 3, c = idx & 7;
        const __half* g = arr ? Bh : Ah;
        int rowbase = arr ? bn : bm;
        uint32_t region = arr ? ST_B : ST_A;
        uint32_t dst = stg + region + (uint32_t)(r * 128 + ((c ^ (r & 7)) << 4));
        CP16(dst, &g[(size_t)(rowbase + r) * DM + koff + c * 8]);
    }
    CP_COMMIT();
}

template <bool HALF_OUT>
__device__ __forceinline__ void tc_gemm_body(char* smem,
                                             const __half* __restrict__ Ah,
                                             const __half* __restrict__ Bh,
                                             void* __restrict__ Cp,
                                             int bm, int bn) {
    uint32_t sb = smem_u32(smem);
    int tid = threadIdx.x;             // 256
    int wid = tid >> 5, lane = tid & 31;
    int warp_m = wid & 3, warp_n = wid >> 2;       // 4 x 2 warps -> 32x64 warp tile

    float c[2][8][4];
#pragma unroll
    for (int mt = 0; mt < 2; mt++)
#pragma unroll
        for (int nt = 0; nt < 8; nt++)
#pragma unroll
            for (int e = 0; e < 4; e++) c[mt][nt][e] = 0.0f;

    int arow = warp_m * 32 + (lane & 15);
    int akh  = lane >> 4;
    int axor = arow & 7;
    int brow = warp_n * 64 + (lane & 7) + ((lane >> 4) << 3);
    int bkh  = (lane >> 3) & 1;
    int bxor = brow & 7;

    stage_load(sb, 0, 0,   tid, Ah, Bh, bm, bn);
    stage_load(sb, 1, BKC, tid, Ah, Bh, bm, bn);

    for (int kc = 0; kc < NCH; kc++) {
        if (kc == NCH - 1) { CP_WAIT(0); } else { CP_WAIT(1); }
        __syncthreads();
        if (kc + 2 < NCH)
            stage_load(sb, (kc + 2) % NSTG, (kc + 2) * BKC, tid, Ah, Bh, bm, bn);

        uint32_t stg = sb + (uint32_t)(kc % NSTG) * STAGE;
#pragma unroll
        for (int ks = 0; ks < 4; ks++) {
            uint32_t ach = (uint32_t)(((ks * 2 + akh) ^ axor) << 4);
            uint32_t bch = (uint32_t)(((ks * 2 + bkh) ^ bxor) << 4);
            uint32_t ah[2][4];
#pragma unroll
            for (int mt = 0; mt < 2; mt++)
                ldmx4(ah[mt], stg + ST_A + (uint32_t)((arow + mt * 16) * 128) + ach);
#pragma unroll
            for (int npp = 0; npp < 2; npp++) {
                uint32_t bh0[4], bh1[4];
                ldmx4(bh0, stg + ST_B + (uint32_t)((brow + (npp * 2 + 0) * 16) * 128) + bch);
                ldmx4(bh1, stg + ST_B + (uint32_t)((brow + (npp * 2 + 1) * 16) * 128) + bch);
#pragma unroll
                for (int mt = 0; mt < 2; mt++) {
                    mma16816(c[mt][(npp * 2 + 0) * 2 + 0], ah[mt], &bh0[0]);
                    mma16816(c[mt][(npp * 2 + 0) * 2 + 1], ah[mt], &bh0[2]);
                    mma16816(c[mt][(npp * 2 + 1) * 2 + 0], ah[mt], &bh1[0]);
                    mma16816(c[mt][(npp * 2 + 1) * 2 + 1], ah[mt], &bh1[2]);
                }
            }
        }
        __syncthreads();
    }

    int gid = lane >> 2, t4 = lane & 3;
#pragma unroll
    for (int mt = 0; mt < 2; mt++) {
        int r = bm + warp_m * 32 + mt * 16 + gid;
#pragma unroll
        for (int nt = 0; nt < 8; nt++) {
            int col = bn + warp_n * 64 + nt * 8 + t4 * 2;
            if (HALF_OUT) {
                __half* C = (__half*)Cp;
                *(uint32_t*)&C[(size_t)r * DM + col] =
                    pkh(__float2half(c[mt][nt][0]), __float2half(c[mt][nt][1]));
                *(uint32_t*)&C[(size_t)(r + 8) * DM + col] =
                    pkh(__float2half(c[mt][nt][2]), __float2half(c[mt][nt][3]));
            } else {
                float* C = (float*)Cp;
                *(float2*)&C[(size_t)r * DM + col] =
                    make_float2(c[mt][nt][0], c[mt][nt][1]);
                *(float2*)&C[(size_t)(r + 8) * DM + col] =
                    make_float2(c[mt][nt][2], c[mt][nt][3]);
            }
        }
    }
}

// ---------------- fused: QKV GEMMs (fp16 out) + kNN (smem positions) -------------
#define QW 8
__global__ __launch_bounds__(256, 2) void fused_qkv_knn(__half* __restrict__ Cq,
                                                        __half* __restrict__ Ck,
                                                        __half* __restrict__ Cv) {
    extern __shared__ __align__(128) char smem[];
    int g7 = blockIdx.x / 7, r7 = blockIdx.x % 7;

    if (r7 < 3) {
        int id = g7 * 3 + r7;              // 0..767
        int z  = id >> 8;
        int rem = id & 255;
        int bm = (rem >> 2) * 128, bn = (rem & 3) * 128;
        __half* C = (z == 0) ? Cq : (z == 1) ? Ck : Cv;
        tc_gemm_body<true>(smem, g_Ah, g_Bh + (size_t)z * DM * DM, C, bm, bn);
    } else {
        // ---- kNN CTA: smem-resident positions, warp per query -------------------
        float4* spos = (float4*)smem;                       // 4096 x 16B = 64KB
        int warp = threadIdx.x >> 5, lane = threadIdx.x & 31;
        int qbase = (g7 * 4 + (r7 - 3)) * QW;               // 8 queries, same batch
        int q = qbase + warp;
        int b = qbase >> 12;
        int base = b << 12;

        for (int i = threadIdx.x; i < NPTS; i += 256)
            spos[i] = g_pos4[base + i];
        __syncthreads();

        float4 qp = spos[q - base];

        unsigned long long key[KNB + 1];
#pragma unroll
        for (int i = 0; i < KNB + 1; i++) key[i] = 0xFFFFFFFFFFFFFFFFull;
        unsigned long long Tb = 0xFFFFFFFFFFFFFFFFull;

        for (int step = 0; step < NPTS / 32; step++) {
            if ((step & 7) == 0) {
                unsigned long long w = key[KNB];
#pragma unroll
                for (int off = 16; off; off >>= 1) {
                    unsigned long long o = __shfl_xor_sync(0xffffffffu, w, off);
                    if (o < w) w = o;
                }
                Tb = w;
            }
            int j = step * 32 + lane;
            float4 p = spos[j];
            float dx = qp.x - p.x;
            float dy = qp.y - p.y;
            float dz = qp.z - p.z;
            float d = fmaf(dx, dx, fmaf(dy, dy, dz * dz));
            unsigned long long kk =
                ((unsigned long long)__float_as_uint(d) << 32) | (unsigned)j;
            if (kk < Tb) {
#pragma unroll
                for (int p2 = KNB; p2 >= 1; p2--) {
                    unsigned long long lower = key[p2 - 1];
                    unsigned long long cur   = key[p2];
                    key[p2] = (kk >= cur) ? cur : ((kk >= lower) ? kk : lower);
                }
                key[0] = (kk < key[0]) ? kk : key[0];
            }
        }

        __syncthreads();
        unsigned long long (*smrg)[32][KNB + 2] =
            (unsigned long long (*)[32][KNB + 2])smem;
#pragma unroll
        for (int i = 0; i < KNB + 1; i++) smrg[warp][lane][i] = key[i];
        smrg[warp][lane][KNB + 1] = 0xFFFFFFFFFFFFFFFFull;
        __syncwarp();

        int p = 0;
        unsigned long long head = smrg[warp][lane][0];
        for (int out = 0; out < KNB + 1; out++) {
            unsigned long long m = head;
#pragma unroll
            for (int off = 16; off; off >>= 1) {
                unsigned long long o = __shfl_xor_sync(0xffffffffu, m, off);
                if (o < m) m = o;
            }
            if (out > 0 && lane == 0)
                g_idx[q * KNB + out - 1] = (int)(unsigned)m;
            if (head == m) { p++; head = smrg[warp][lane][p]; }
        }
    }
}

__global__ __launch_bounds__(256, 2) void gemm_o_tc(float* __restrict__ C) {
    extern __shared__ __align__(128) char smem[];
    tc_gemm_body<false>(smem, g_Ah, g_Bh + (size_t)3 * DM * DM,
                        C, blockIdx.y * 128, blockIdx.x * 128);
}

// ---------------- attention: warp per (row, head), full-MLP, dual chains ---------
__global__ __launch_bounds__(256) void attn_kernel(const float* __restrict__ Wpos,
                                                   const float* __restrict__ bpos,
                                                   const float* __restrict__ temp) {
    int gw   = (blockIdx.x * blockDim.x + threadIdx.x) >> 5;
    int lane = threadIdx.x & 31;
    int row  = gw >> 3;
    int h    = gw & 7;
    int b    = row >> 12;
    int base = (b << 12);

    int j = 0;
    float rx = 0.f, ry = 0.f, rz = 0.f;
    float4 qp = g_pos4[row];
    if (lane < KNB) {
        j  = g_idx[row * KNB + lane];
        float4 p = g_pos4[base + j];
        rx = qp.x - p.x; ry = qp.y - p.y; rz = qp.z - p.z;
    }

    int jks[KNB];
#pragma unroll
    for (int k = 0; k < KNB; k++)
        jks[k] = __shfl_sync(0xffffffffu, j, k);

    // hoist ALL gathered loads (16 K + 16 V): 32 outstanding sectors
    __half2 kvh[KNB], vvh[KNB];
#pragma unroll
    for (int k = 0; k < KNB; k++)
        kvh[k] = *(const __half2*)&g_Kh[(size_t)(base + jks[k]) * DM + h * DH + 2 * lane];
#pragma unroll
    for (int k = 0; k < KNB; k++)
        vvh[k] = *(const __half2*)&g_Vh[(size_t)(base + jks[k]) * DM + h * DH + 2 * lane];

    float invT = 1.0f / temp[0];
    float2 q = __half22float2(*(const __half2*)&g_Qh[(size_t)row * DM + h * DH + 2 * lane]);
    q.x *= invT; q.y *= invT;
    float2 w0 = *(const float2*)&Wpos[0 * 128 + 2 * lane];
    float2 w1 = *(const float2*)&Wpos[1 * 128 + 2 * lane];
    float2 w2 = *(const float2*)&Wpos[2 * 128 + 2 * lane];
    float2 bp = *(const float2*)&bpos[2 * lane];

    // separable pe dot products (all-lane reduce)
    float pa = fmaf(q.x, w0.x, q.y * w0.y);
    float pb = fmaf(q.x, w1.x, q.y * w1.y);
    float pc = fmaf(q.x, w2.x, q.y * w2.y);
    float pd = fmaf(q.x, bp.x, q.y * bp.y);
#pragma unroll
    for (int off = 16; off; off >>= 1) {
        pa += __shfl_xor_sync(0xffffffffu, pa, off);
        pb += __shfl_xor_sync(0xffffffffu, pb, off);
        pc += __shfl_xor_sync(0xffffffffu, pc, off);
        pd += __shfl_xor_sync(0xffffffffu, pd, off);
    }

    // score reductions: pairs (k, k+8) -> two independent shfl chains in flight
    float myscore = 0.0f;
#pragma unroll
    for (int k = 0; k < KNB / 2; k++) {
        float2 ka = __half22float2(kvh[k]);
        float2 kb = __half22float2(kvh[k + 8]);
        float s0 = fmaf(q.x, ka.x, q.y * ka.y);
        float s1 = fmaf(q.x, kb.x, q.y * kb.y);
#pragma unroll
        for (int off = 16; off; off >>= 1) {
            s0 += __shfl_xor_sync(0xffffffffu, s0, off);
            s1 += __shfl_xor_sync(0xffffffffu, s1, off);
        }
        if (lane == k)     myscore = s0;
        if (lane == k + 8) myscore = s1;
    }
    myscore += fmaf(rx, pa, fmaf(ry, pb, fmaf(rz, pc, pd)));

    float sc = (lane < KNB) ? myscore : -INFINITY;
    float m = sc;
#pragma unroll
    for (int off = 8; off; off >>= 1)
        m = fmaxf(m, __shfl_xor_sync(0xffffffffu, m, off));
    float e = (lane < KNB) ? __expf(sc - m) : 0.0f;
    float sum = e;
#pragma unroll
    for (int off = 8; off; off >>= 1)
        sum += __shfl_xor_sync(0xffffffffu, sum, off);
    float w = e / sum;

    float2 acc = make_float2(0.f, 0.f);
#pragma unroll
    for (int k = 0; k < KNB; k++) {
        float wk = __shfl_sync(0xffffffffu, w, k);
        float2 v = __half22float2(vvh[k]);
        acc.x = fmaf(wk, v.x, acc.x);
        acc.y = fmaf(wk, v.y, acc.y);
    }
    size_t off = (size_t)row * DM + h * DH + 2 * lane;
    *(uint32_t*)&g_Ah[off] = pkh(__float2half(acc.x), __float2half(acc.y));
}

// ---------------- epilogue: warp-per-row +bo, +residual, LayerNorm ---------------
__global__ __launch_bounds__(256) void ln_kernel(const float* __restrict__ feat,
                                                 const float* __restrict__ bo,
                                                 const float* __restrict__ gamma,
                                                 const float* __restrict__ beta,
                                                 float* __restrict__ out) {
    int warp = threadIdx.x >> 5, lane = threadIdx.x & 31;
    int row  = blockIdx.x * 8 + warp;          // 1024 CTAs x 8 warps

    float4 x[4];
    float s = 0.0f;
#pragma unroll
    for (int i = 0; i < 4; i++) {
        int col = lane * 4 + i * 128;
        float4 a = *(const float4*)&g_tmp[(size_t)row * DM + col];
        float4 f = *(const float4*)&feat[(size_t)row * DM + col];
        float4 bb = *(const float4*)&bo[col];
        x[i] = make_float4(a.x + f.x + bb.x, a.y + f.y + bb.y,
                           a.z + f.z + bb.z, a.w + f.w + bb.w);
        s += x[i].x + x[i].y + x[i].z + x[i].w;
    }
#pragma unroll
    for (int o = 16; o; o >>= 1) s += __shfl_xor_sync(0xffffffffu, s, o);
    float mu = s * (1.0f / DM);

    float v = 0.0f;
#pragma unroll
    for (int i = 0; i < 4; i++) {
        float dx = x[i].x - mu, dy = x[i].y - mu, dz = x[i].z - mu, dw = x[i].w - mu;
        v += dx * dx + dy * dy + dz * dz + dw * dw;
    }
#pragma unroll
    for (int o = 16; o; o >>= 1) v += __shfl_xor_sync(0xffffffffu, v, o);
    float rs = rsqrtf(v * (1.0f / DM) + 1e-5f);

#pragma unroll
    for (int i = 0; i < 4; i++) {
        int col = lane * 4 + i * 128;
        float4 g = *(const float4*)&gamma[col];
        float4 be = *(const float4*)&beta[col];
        float4 o4;
        o4.x = (x[i].x - mu) * rs * g.x + be.x;
        o4.y = (x[i].y - mu) * rs * g.y + be.y;
        o4.z = (x[i].z - mu) * rs * g.z + be.z;
        o4.w = (x[i].w - mu) * rs * g.w + be.w;
        *(float4*)&out[(size_t)row * DM + col] = o4;
    }
}

// ---------------- launch ---------------------------------------------------------
extern "C" void kernel_launch(void* const* d_in, const int* in_sizes, int n_in,
                              void* d_out, int out_size) {
    const float* pos   = (const float*)d_in[0];
    const float* feat  = (const float*)d_in[1];
    const float* Wq    = (const float*)d_in[3];
    const float* Wk    = (const float*)d_in[4];
    const float* Wv    = (const float*)d_in[5];
    const float* Wo    = (const float*)d_in[6];
    const float* bo    = (const float*)d_in[7];
    const float* Wpos  = (const float*)d_in[8];
    const float* bpos  = (const float*)d_in[9];
    const float* temp  = (const float*)d_in[10];
    const float* gamma = (const float*)d_in[11];
    const float* beta  = (const float*)d_in[12];
    float* out = (float*)d_out;

    __half *pQ, *pK, *pV;
    float *pTmp;
    cudaGetSymbolAddress((void**)&pQ,   g_Qh);
    cudaGetSymbolAddress((void**)&pK,   g_Kh);
    cudaGetSymbolAddress((void**)&pV,   g_Vh);
    cudaGetSymbolAddress((void**)&pTmp, g_tmp);

    cudaFuncSetAttribute(fused_qkv_knn, cudaFuncAttributeMaxDynamicSharedMemorySize, GEMM_SMEM);
    cudaFuncSetAttribute(gemm_o_tc,     cudaFuncAttributeMaxDynamicSharedMemorySize, GEMM_SMEM);

    prep_kernel<<<512 + 1024 + 32, 256>>>(feat, pos, Wq, Wk, Wv, Wo);

    fused_qkv_knn<<<1792, 256, GEMM_SMEM>>>(pQ, pK, pV);

    attn_kernel<<<ROWS * NH * 32 / 256, 256>>>(Wpos, bpos, temp);

    gemm_o_tc<<<dim3(DM / 128, ROWS / 128), 256, GEMM_SMEM>>>(pTmp);

    ln_kernel<<<ROWS / 8, 256>>>(feat, bo, gamma, beta, out);
}